// round 4
// baseline (speedup 1.0000x reference)
#include <cuda_runtime.h>

#define BB 32
#define NVV 8192
#define NEE 65536
#define ELLMAX 48
#define NSUB 8
#define NCTA 8          // CTAs per batch
#define TPB 512
#define VPC 1024        // vertices per CTA
#define VPT 2           // vertices per thread
#define CG_ITERS 20
#define DTf 0.01f
#define KSf 10000.0f
#define CS (BB*NVV)     // planar SoA component stride

// ---------------- scratch (static device globals) ---------------------------
__device__ float g_pos[3*CS];
__device__ float g_v0 [3*CS];
__device__ float g_r  [3*CS];
__device__ int   g_cnt[NVV];
__device__ int   g_deg[NVV];
__device__ int   g_nbr[ELLMAX*NVV];
__device__ int   g_eid[ELLMAX*NVV];
__device__ float g_rest[(size_t)BB*ELLMAX*NVV];   // [b][k][v]
__device__ float g_rs [2][BB][NCTA];
__device__ float g_pAp[BB][NCTA];
__device__ int   g_bar[BB];

// ---------------- helpers ---------------------------------------------------
// 512-thread block reduce; result valid on thread 0
__device__ __forceinline__ float bred(float v, float* s16) {
    int lane = threadIdx.x & 31, w = threadIdx.x >> 5;
    #pragma unroll
    for (int o = 16; o > 0; o >>= 1) v += __shfl_down_sync(0xffffffffu, v, o);
    if (lane == 0) s16[w] = v;
    __syncthreads();
    if (threadIdx.x < 16) {
        v = s16[threadIdx.x];
        #pragma unroll
        for (int o = 8; o > 0; o >>= 1) v += __shfl_down_sync(0xffffu, v, o);
    }
    return v;
}

// per-batch barrier over NCTA CTAs; ph is a monotonically increasing phase no.
__device__ __forceinline__ void batch_barrier(int b, int ph) {
    __syncthreads();
    __threadfence();
    if (threadIdx.x == 0) {
        atomicAdd(&g_bar[b], 1);
        int target = NCTA * ph;
        volatile int* c = (volatile int*)&g_bar[b];
        while (*c < target) { }
    }
    __syncthreads();
}

// ---------------- setup ------------------------------------------------------
__global__ void k_zero() {
    int v = blockIdx.x * blockDim.x + threadIdx.x;
    if (v < NVV) g_cnt[v] = 0;
    if (v < BB)  g_bar[v] = 0;
}

__global__ void k_init(const float* __restrict__ pos0, const float* __restrict__ vel0) {
    int i = blockIdx.x * blockDim.x + threadIdx.x;   // i = b*NVV + v
    if (i >= CS) return;
    #pragma unroll
    for (int c = 0; c < 3; c++) {
        g_pos[c*CS + i] = pos0[i*3 + c];
        g_v0 [c*CS + i] = vel0[i*3 + c];
    }
}

__global__ void k_fill(const int* __restrict__ ei, const int* __restrict__ ej) {
    int e = blockIdx.x * blockDim.x + threadIdx.x;
    if (e >= NEE) return;
    int i = ei[e], j = ej[e];
    int si = atomicAdd(&g_cnt[i], 1);
    if (si < ELLMAX) { g_nbr[si*NVV + i] = j; g_eid[si*NVV + i] = e; }
    int sj = atomicAdd(&g_cnt[j], 1);
    if (sj < ELLMAX) { g_nbr[sj*NVV + j] = i; g_eid[sj*NVV + j] = e; }
}

// deterministic adjacency order per vertex
__global__ void k_sort() {
    int v = blockIdx.x * blockDim.x + threadIdx.x;
    if (v >= NVV) return;
    int d = min(g_cnt[v], ELLMAX);
    g_deg[v] = d;
    long long key[ELLMAX];
    for (int k = 0; k < d; k++)
        key[k] = ((long long)g_nbr[k*NVV + v] << 32) | (unsigned)g_eid[k*NVV + v];
    for (int a = 1; a < d; a++) {
        long long t = key[a]; int c = a - 1;
        while (c >= 0 && key[c] > t) { key[c+1] = key[c]; c--; }
        key[c+1] = t;
    }
    for (int k = 0; k < d; k++) {
        g_nbr[k*NVV + v] = (int)(key[k] >> 32);
        g_eid[k*NVV + v] = (int)(key[k] & 0xffffffffLL);
    }
}

__global__ void k_rest(const float* __restrict__ rest_len, const float* __restrict__ act) {
    int v = blockIdx.x * blockDim.x + threadIdx.x;
    int b = blockIdx.y;
    if (v >= NVV) return;
    int d = g_deg[v];
    for (int k = 0; k < d; k++) {
        int e = g_eid[k*NVV + v];
        g_rest[((size_t)b*ELLMAX + k)*NVV + v] = rest_len[e] * (1.f + act[(size_t)b*NEE + e]);
    }
}

// ---------------- the persistent solver --------------------------------------
__global__ void __launch_bounds__(TPB, 2) k_main(const float* __restrict__ mass,
                                                 float* __restrict__ out) {
    extern __shared__ float sm[];
    float2* s_xy = (float2*)sm;          // 64 KB  (p.x, p.y / pos.x, pos.y)
    float*  s_z  = sm + 2*NVV;           // 32 KB
    __shared__ float s16[16];

    const int tid = threadIdx.x, cx = blockIdx.x, b = blockIdx.y;
    const int base = b*NVV;
    int ph = 0;

    // persistent per-thread state (own slice: 2 vertices)
    int   vv[VPT]; float mm[VPT]; int dd[VPT];
    float X[VPT][3];   // velocity / CG x
    float R[VPT][3];   // CG residual
    float PO[VPT][3];  // position
    #pragma unroll
    for (int q = 0; q < VPT; q++) {
        int v = cx*VPC + q*TPB + tid;
        vv[q] = v; mm[q] = mass[v]; dd[q] = g_deg[v];
        int i = base + v;
        PO[q][0] = g_pos[i]; PO[q][1] = g_pos[CS+i]; PO[q][2] = g_pos[2*CS+i];
        X [q][0] = g_v0[i];  X [q][1] = g_v0[CS+i];  X [q][2] = g_v0[2*CS+i];
    }

    for (int s = 0; s < NSUB; s++) {
        // ---------- Phase A: stage pos, compute force, b = m v + dt f -------
        #pragma unroll
        for (int j = 0; j < VPC/TPB*NCTA; j++) {       // 16 chunks -> full vector
            int v = j*TPB + tid, i = base + v;
            s_xy[v] = make_float2(__ldcg(&g_pos[i]), __ldcg(&g_pos[CS+i]));
            s_z [v] = __ldcg(&g_pos[2*CS+i]);
        }
        __syncthreads();

        float rs_part = 0.f;
        #pragma unroll
        for (int q = 0; q < VPT; q++) {
            int v = vv[q], i = base + v, d = dd[q];
            float px = PO[q][0], py = PO[q][1], pz = PO[q][2];
            float fx = 0.f, fy = 0.f, fz = 0.f;
            for (int k = 0; k < d; k++) {
                int u = g_nbr[k*NVV + v];
                float2 t = s_xy[u];
                float dx = px - t.x, dy = py - t.y, dz = pz - s_z[u];
                float l  = sqrtf(dx*dx + dy*dy + dz*dz);
                float rr = g_rest[((size_t)b*ELLMAX + k)*NVV + v];
                float c  = -KSf * (l - rr) / fmaxf(l, 1e-6f);
                fx += c*dx; fy += c*dy; fz += c*dz;
            }
            fy += mm[q] * (-9.8f);
            float bx = mm[q]*X[q][0] + DTf*fx;
            float by = mm[q]*X[q][1] + DTf*fy;
            float bz = mm[q]*X[q][2] + DTf*fz;
            R[q][0] = bx; R[q][1] = by; R[q][2] = bz;
            X[q][0] = 0.f; X[q][1] = 0.f; X[q][2] = 0.f;
            __stcg(&g_r[i], bx); __stcg(&g_r[CS+i], by); __stcg(&g_r[2*CS+i], bz);
            rs_part += bx*bx + by*by + bz*bz;
        }
        {
            float t = bred(rs_part, s16);
            if (tid == 0) __stcg(&g_rs[0][b][cx], t);
        }
        batch_barrier(b, ++ph);

        // ---------- CG iterations -------------------------------------------
        for (int it = 0; it < CG_ITERS; it++) {
            const int cur = it & 1;

            // Phase B: p = r + beta*p (p in smem), matvec, pAp partials
            if (it == 0) {
                #pragma unroll
                for (int j = 0; j < 16; j++) {
                    int v = j*TPB + tid, i = base + v;
                    s_xy[v] = make_float2(__ldcg(&g_r[i]), __ldcg(&g_r[CS+i]));
                    s_z [v] = __ldcg(&g_r[2*CS+i]);
                }
            } else {
                float rsn = 0.f, rso = 0.f;
                #pragma unroll
                for (int k = 0; k < NCTA; k++) {
                    rsn += __ldcg(&g_rs[cur][b][k]);
                    rso += __ldcg(&g_rs[cur^1][b][k]);
                }
                float beta = rsn / (rso + 1e-12f);
                #pragma unroll
                for (int j = 0; j < 16; j++) {
                    int v = j*TPB + tid, i = base + v;
                    float2 o2 = s_xy[v]; float oz = s_z[v];
                    s_xy[v] = make_float2(fmaf(beta, o2.x, __ldcg(&g_r[i])),
                                          fmaf(beta, o2.y, __ldcg(&g_r[CS+i])));
                    s_z [v] = fmaf(beta, oz, __ldcg(&g_r[2*CS+i]));
                }
            }
            __syncthreads();

            float Ap[VPT][3];
            float pap = 0.f;
            #pragma unroll
            for (int q = 0; q < VPT; q++) {
                int v = vv[q], d = dd[q];
                float sx = 0.f, sy = 0.f, sz = 0.f;
                for (int k = 0; k < d; k++) {
                    int u = g_nbr[k*NVV + v];
                    float2 t = s_xy[u];
                    sx += t.x; sy += t.y; sz += s_z[u];
                }
                float2 pv = s_xy[v]; float pz = s_z[v];
                float df = (float)d;
                Ap[q][0] = mm[q]*pv.x + (df*pv.x - sx);
                Ap[q][1] = mm[q]*pv.y + (df*pv.y - sy);
                Ap[q][2] = mm[q]*pz   + (df*pz   - sz);
                pap += pv.x*Ap[q][0] + pv.y*Ap[q][1] + pz*Ap[q][2];
            }
            {
                float t = bred(pap, s16);
                if (tid == 0) __stcg(&g_pAp[b][cx], t);
            }
            batch_barrier(b, ++ph);

            // Phase C: alpha; x += a p; r -= a Ap; rs_new partials
            float rs = 0.f, paps = 0.f;
            #pragma unroll
            for (int k = 0; k < NCTA; k++) {
                rs   += __ldcg(&g_rs[cur][b][k]);
                paps += __ldcg(&g_pAp[b][k]);
            }
            float alpha = rs / (paps + 1e-12f);
            const bool last = (it == CG_ITERS - 1);
            float rsn_part = 0.f;
            #pragma unroll
            for (int q = 0; q < VPT; q++) {
                int v = vv[q], i = base + v;
                float2 pv = s_xy[v]; float pz = s_z[v];
                X[q][0] += alpha*pv.x; X[q][1] += alpha*pv.y; X[q][2] += alpha*pz;
                R[q][0] -= alpha*Ap[q][0];
                R[q][1] -= alpha*Ap[q][1];
                R[q][2] -= alpha*Ap[q][2];
                rsn_part += R[q][0]*R[q][0] + R[q][1]*R[q][1] + R[q][2]*R[q][2];
                if (!last) {
                    __stcg(&g_r[i],      R[q][0]);
                    __stcg(&g_r[CS+i],   R[q][1]);
                    __stcg(&g_r[2*CS+i], R[q][2]);
                }
            }
            {
                float t = bred(rsn_part, s16);
                if (tid == 0) __stcg(&g_rs[cur^1][b][cx], t);
            }
            if (last) {
                #pragma unroll
                for (int q = 0; q < VPT; q++) {
                    int v = vv[q], i = base + v;
                    PO[q][0] += DTf*X[q][0];
                    PO[q][1] += DTf*X[q][1];
                    PO[q][2] += DTf*X[q][2];
                    __stcg(&g_pos[i],      PO[q][0]);
                    __stcg(&g_pos[CS+i],   PO[q][1]);
                    __stcg(&g_pos[2*CS+i], PO[q][2]);
                    size_t o = (((size_t)b*NSUB + s)*NVV + v)*3;
                    out[o+0] = PO[q][0]; out[o+1] = PO[q][1]; out[o+2] = PO[q][2];
                }
            }
            batch_barrier(b, ++ph);
        }
    }
}

// ---------------- launch ----------------------------------------------------
extern "C" void kernel_launch(void* const* d_in, const int* in_sizes, int n_in,
                              void* d_out, int out_size) {
    const float* act   = (const float*)d_in[0];
    const float* pos0  = (const float*)d_in[1];
    const float* vel0  = (const float*)d_in[2];
    const float* rlen  = (const float*)d_in[3];
    const float* mass  = (const float*)d_in[4];
    const int*   ei    = (const int*)d_in[5];
    const int*   ej    = (const int*)d_in[6];
    float*       out   = (float*)d_out;

    const int smbytes = NVV*sizeof(float2) + NVV*sizeof(float);   // 96 KB
    static int attr_done = 0;
    if (!attr_done) {
        cudaFuncSetAttribute(k_main, cudaFuncAttributeMaxDynamicSharedMemorySize, smbytes);
        attr_done = 1;
    }

    k_zero<<<(NVV+255)/256, 256>>>();
    k_init<<<(CS+255)/256, 256>>>(pos0, vel0);
    k_fill<<<(NEE+255)/256, 256>>>(ei, ej);
    k_sort<<<(NVV+127)/128, 128>>>();
    k_rest<<<dim3(NVV/256, BB), 256>>>(rlen, act);

    k_main<<<dim3(NCTA, BB), TPB, smbytes>>>(mass, out);
}

// round 6
// speedup vs baseline: 1.1602x; 1.1602x over previous
#include <cuda_runtime.h>

#define BB 32
#define NVV 8192
#define NEE 65536
#define ELLMAX 48
#define NSUB 8
#define NCTA 4          // CTAs per batch (128 total, occ 1, all resident)
#define TPB 512
#define VPC 2048        // vertices per CTA
#define VPT 4           // vertices per thread
#define CG_ITERS 20
#define DTf 0.01f
#define KSf 10000.0f
#define CS (BB*NVV)     // planar SoA component stride

// ---------------- scratch (static device globals) ---------------------------
__device__ float    g_pos[3*CS];
__device__ float    g_v0 [3*CS];
__device__ float    g_r  [3*CS];
__device__ float    g_Apb[2][3*CS];               // double-buffered Ap
__device__ int      g_cnt[NVV];
__device__ int      g_deg[NVV];
__device__ int      g_nbr[ELLMAX*NVV];
__device__ int      g_eid[ELLMAX*NVV];
__device__ float    g_rest[(size_t)BB*ELLMAX*NVV]; // [b][k][v]
__device__ float    g_pAp[2][BB][NCTA];           // pAp partials (parity-buffered)
__device__ unsigned g_bar[BB];

// ---------------- helpers ---------------------------------------------------
__device__ __forceinline__ void batch_barrier(unsigned* bar, unsigned target) {
    __syncthreads();
    if (threadIdx.x == 0) {
        asm volatile("red.release.gpu.add.u32 [%0], 1;" :: "l"(bar) : "memory");
        unsigned v;
        do {
            asm volatile("ld.acquire.gpu.u32 %0, [%1];" : "=r"(v) : "l"(bar) : "memory");
        } while (v < target);
    }
    __syncthreads();
}

// reduce over 512 threads; result valid on thread 0 (deterministic tree)
__device__ __forceinline__ float bred1(float a, float* s16) {
    int lane = threadIdx.x & 31, w = threadIdx.x >> 5;
    #pragma unroll
    for (int o = 16; o; o >>= 1) a += __shfl_down_sync(0xffffffffu, a, o);
    if (lane == 0) s16[w] = a;
    __syncthreads();
    float r = 0.f;
    if (threadIdx.x == 0) {
        #pragma unroll
        for (int k = 0; k < 16; k++) r += s16[k];
    }
    return r;
}

// ---------------- setup ------------------------------------------------------
__global__ void k_zero() {
    int v = blockIdx.x * blockDim.x + threadIdx.x;
    if (v < NVV) g_cnt[v] = 0;
    if (v < BB)  g_bar[v] = 0u;
}

__global__ void k_init(const float* __restrict__ pos0, const float* __restrict__ vel0) {
    int i = blockIdx.x * blockDim.x + threadIdx.x;
    if (i >= CS) return;
    #pragma unroll
    for (int c = 0; c < 3; c++) {
        g_pos[c*CS + i] = pos0[i*3 + c];
        g_v0 [c*CS + i] = vel0[i*3 + c];
    }
}

__global__ void k_fill(const int* __restrict__ ei, const int* __restrict__ ej) {
    int e = blockIdx.x * blockDim.x + threadIdx.x;
    if (e >= NEE) return;
    int i = ei[e], j = ej[e];
    int si = atomicAdd(&g_cnt[i], 1);
    if (si < ELLMAX) { g_nbr[si*NVV + i] = j; g_eid[si*NVV + i] = e; }
    int sj = atomicAdd(&g_cnt[j], 1);
    if (sj < ELLMAX) { g_nbr[sj*NVV + j] = i; g_eid[sj*NVV + j] = e; }
}

__global__ void k_sort() {
    int v = blockIdx.x * blockDim.x + threadIdx.x;
    if (v >= NVV) return;
    int d = min(g_cnt[v], ELLMAX);
    g_deg[v] = d;
    long long key[ELLMAX];
    for (int k = 0; k < d; k++)
        key[k] = ((long long)g_nbr[k*NVV + v] << 32) | (unsigned)g_eid[k*NVV + v];
    for (int a = 1; a < d; a++) {
        long long t = key[a]; int c = a - 1;
        while (c >= 0 && key[c] > t) { key[c+1] = key[c]; c--; }
        key[c+1] = t;
    }
    for (int k = 0; k < d; k++) {
        g_nbr[k*NVV + v] = (int)(key[k] >> 32);
        g_eid[k*NVV + v] = (int)(key[k] & 0xffffffffLL);
    }
}

__global__ void k_rest(const float* __restrict__ rest_len, const float* __restrict__ act) {
    int v = blockIdx.x * blockDim.x + threadIdx.x;
    int b = blockIdx.y;
    if (v >= NVV) return;
    int d = g_deg[v];
    for (int k = 0; k < d; k++) {
        int e = g_eid[k*NVV + v];
        g_rest[((size_t)b*ELLMAX + k)*NVV + v] = rest_len[e] * (1.f + act[(size_t)b*NEE + e]);
    }
}

// ---------------- persistent solver ------------------------------------------
__global__ void __launch_bounds__(TPB, 1) k_main(const float* __restrict__ mass,
                                                 float* __restrict__ out) {
    extern __shared__ float sm[];
    float2* s_pxy = (float2*)sm;          // p.xy  (64 KB)
    float*  s_pz  = sm + 16384;           // p.z   (32 KB)
    float*  s_rx  = sm + 24576;           // r     (96 KB)
    float*  s_ry  = sm + 32768;
    float*  s_rz  = sm + 40960;
    __shared__ float s16[16];
    __shared__ float s_ab[2];             // alpha, beta broadcast
    __shared__ float s_rs;                // current ||r||^2 (identical in all CTAs)

    const int tid = threadIdx.x, cx = blockIdx.x, b = blockIdx.y;
    const int base = b*NVV;
    unsigned* bar = &g_bar[b];
    unsigned ph = 0;

    float PO[VPT][3], X[VPT][3], mm[VPT];
    int dd[VPT];
    #pragma unroll
    for (int q = 0; q < VPT; q++) {
        int v = cx*VPC + q*TPB + tid, i = base + v;
        mm[q] = mass[v]; dd[q] = g_deg[v];
        PO[q][0] = g_pos[i]; PO[q][1] = g_pos[CS+i]; PO[q][2] = g_pos[2*CS+i];
        X [q][0] = g_v0[i];  X [q][1] = g_v0[CS+i];  X [q][2] = g_v0[2*CS+i];
    }

    for (int s = 0; s < NSUB; s++) {
        // ---- stage pos into P region ------------------------------------
        #pragma unroll
        for (int j = 0; j < 16; j++) {
            int v = j*TPB + tid, i = base + v;
            s_pxy[v] = make_float2(__ldcg(&g_pos[i]), __ldcg(&g_pos[CS+i]));
            s_pz [v] = __ldcg(&g_pos[2*CS+i]);
        }
        __syncthreads();

        // ---- force, b = m v + dt f (own slice -> g_r) -------------------
        #pragma unroll
        for (int q = 0; q < VPT; q++) {
            int v = cx*VPC + q*TPB + tid, i = base + v, d = dd[q];
            float px = PO[q][0], py = PO[q][1], pz = PO[q][2];
            float fx = 0.f, fy = 0.f, fz = 0.f;
            for (int k = 0; k < d; k++) {
                int u = g_nbr[k*NVV + v];
                float2 t = s_pxy[u];
                float dx = px - t.x, dy = py - t.y, dz = pz - s_pz[u];
                float l  = sqrtf(dx*dx + dy*dy + dz*dz);
                float rr = g_rest[((size_t)b*ELLMAX + k)*NVV + v];
                float c  = -KSf * (l - rr) / fmaxf(l, 1e-6f);
                fx += c*dx; fy += c*dy; fz += c*dz;
            }
            fy += mm[q] * (-9.8f);
            float bx = mm[q]*X[q][0] + DTf*fx;
            float by = mm[q]*X[q][1] + DTf*fy;
            float bz = mm[q]*X[q][2] + DTf*fz;
            X[q][0] = 0.f; X[q][1] = 0.f; X[q][2] = 0.f;
            __stcg(&g_r[i], bx); __stcg(&g_r[CS+i], by); __stcg(&g_r[2*CS+i], bz);
        }
        batch_barrier(bar, NCTA * (++ph));

        // ---- stage full r into RS and P; rs0 computed locally ------------
        float rs_loc = 0.f;
        #pragma unroll
        for (int j = 0; j < 16; j++) {
            int v = j*TPB + tid, i = base + v;
            float rx = __ldcg(&g_r[i]);
            float ry = __ldcg(&g_r[CS+i]);
            float rz = __ldcg(&g_r[2*CS+i]);
            s_rx[v] = rx; s_ry[v] = ry; s_rz[v] = rz;
            s_pxy[v] = make_float2(rx, ry); s_pz[v] = rz;
            rs_loc += rx*rx + ry*ry + rz*rz;
        }
        __syncthreads();
        {
            float t = bred1(rs_loc, s16);     // full-vector sum: identical in all CTAs
            if (tid == 0) s_rs = t;
        }
        __syncthreads();

        // ---- CG iterations (ONE cross-CTA barrier each) ------------------
        for (int it = 0; it < CG_ITERS; it++) {
            const int par = it & 1;
            float* Ap = g_Apb[par];

            // Phase B: Ap own slice + pAp partial
            float pap = 0.f;
            #pragma unroll
            for (int q = 0; q < VPT; q++) {
                int v = cx*VPC + q*TPB + tid, i = base + v, d = dd[q];
                float sx = 0.f, sy = 0.f, sz = 0.f;
                for (int k = 0; k < d; k++) {
                    int u = g_nbr[k*NVV + v];
                    float2 t = s_pxy[u];
                    sx += t.x; sy += t.y; sz += s_pz[u];
                }
                float2 pv = s_pxy[v]; float pz = s_pz[v];
                float df = (float)d;
                float ax = mm[q]*pv.x + (df*pv.x - sx);
                float ay = mm[q]*pv.y + (df*pv.y - sy);
                float az = mm[q]*pz   + (df*pz   - sz);
                __stcg(&Ap[i], ax); __stcg(&Ap[CS+i], ay); __stcg(&Ap[2*CS+i], az);
                pap += pv.x*ax + pv.y*ay + pz*az;
            }
            {
                float t = bred1(pap, s16);
                if (tid == 0) __stcg(&g_pAp[par][b][cx], t);
            }
            batch_barrier(bar, NCTA * (++ph));

            // alpha (identical in all CTAs: fixed-order sum of canonical partials)
            if (tid == 0) {
                float sp = 0.f;
                #pragma unroll
                for (int k = 0; k < NCTA; k++) sp += __ldcg(&g_pAp[par][b][k]);
                s_ab[0] = s_rs / (sp + 1e-12f);
            }
            __syncthreads();
            float alpha = s_ab[0];

            // x += alpha p  (own slice, p from smem)
            #pragma unroll
            for (int q = 0; q < VPT; q++) {
                int v = cx*VPC + q*TPB + tid;
                float2 pv = s_pxy[v];
                X[q][0] += alpha*pv.x; X[q][1] += alpha*pv.y; X[q][2] += alpha*s_pz[v];
            }

            if (it < CG_ITERS - 1) {
                // pass 1: r -= alpha Ap (full vector, in smem); rs_new locally
                float rsn_loc = 0.f;
                #pragma unroll
                for (int j = 0; j < 16; j++) {
                    int v = j*TPB + tid, i = base + v;
                    float rx = s_rx[v] - alpha*__ldcg(&Ap[i]);
                    float ry = s_ry[v] - alpha*__ldcg(&Ap[CS+i]);
                    float rz = s_rz[v] - alpha*__ldcg(&Ap[2*CS+i]);
                    s_rx[v] = rx; s_ry[v] = ry; s_rz[v] = rz;
                    rsn_loc += rx*rx + ry*ry + rz*rz;
                }
                __syncthreads();
                {
                    float t = bred1(rsn_loc, s16);   // direct ||r_new||^2 — no cancellation
                    if (tid == 0) {
                        s_ab[1] = t / (s_rs + 1e-12f);
                        s_rs = t;
                    }
                }
                __syncthreads();
                float beta = s_ab[1];

                // pass 2: p = r + beta p (full vector, in smem)
                #pragma unroll
                for (int j = 0; j < 16; j++) {
                    int v = j*TPB + tid;
                    float2 po = s_pxy[v]; float poz = s_pz[v];
                    s_pxy[v] = make_float2(fmaf(beta, po.x, s_rx[v]),
                                           fmaf(beta, po.y, s_ry[v]));
                    s_pz [v] = fmaf(beta, poz, s_rz[v]);
                }
                __syncthreads();
            }
        }

        // ---- finish substep: pos += dt x ; emit trajectory ---------------
        #pragma unroll
        for (int q = 0; q < VPT; q++) {
            int v = cx*VPC + q*TPB + tid, i = base + v;
            PO[q][0] += DTf*X[q][0];
            PO[q][1] += DTf*X[q][1];
            PO[q][2] += DTf*X[q][2];
            __stcg(&g_pos[i],      PO[q][0]);
            __stcg(&g_pos[CS+i],   PO[q][1]);
            __stcg(&g_pos[2*CS+i], PO[q][2]);
            size_t o = (((size_t)b*NSUB + s)*NVV + v)*3;
            out[o+0] = PO[q][0]; out[o+1] = PO[q][1]; out[o+2] = PO[q][2];
        }
        batch_barrier(bar, NCTA * (++ph));
    }
}

// ---------------- launch ----------------------------------------------------
extern "C" void kernel_launch(void* const* d_in, const int* in_sizes, int n_in,
                              void* d_out, int out_size) {
    const float* act   = (const float*)d_in[0];
    const float* pos0  = (const float*)d_in[1];
    const float* vel0  = (const float*)d_in[2];
    const float* rlen  = (const float*)d_in[3];
    const float* mass  = (const float*)d_in[4];
    const int*   ei    = (const int*)d_in[5];
    const int*   ej    = (const int*)d_in[6];
    float*       out   = (float*)d_out;

    const int smbytes = 49152 * sizeof(float);   // 192 KB
    static int attr_done = 0;
    if (!attr_done) {
        cudaFuncSetAttribute(k_main, cudaFuncAttributeMaxDynamicSharedMemorySize, smbytes);
        attr_done = 1;
    }

    k_zero<<<(NVV+255)/256, 256>>>();
    k_init<<<(CS+255)/256, 256>>>(pos0, vel0);
    k_fill<<<(NEE+255)/256, 256>>>(ei, ej);
    k_sort<<<(NVV+127)/128, 128>>>();
    k_rest<<<dim3(NVV/256, BB), 256>>>(rlen, act);

    k_main<<<dim3(NCTA, BB), TPB, smbytes>>>(mass, out);
}

// round 7
// speedup vs baseline: 1.1856x; 1.0219x over previous
#include <cuda_runtime.h>

#define BB 32
#define NVV 8192
#define NEE 65536
#define ELLMAX 48
#define NSUB 8
#define NCTA 4          // CTAs per batch (128 total, occ 1, all resident)
#define TPB 512
#define VPC 2048
#define VPT 4
#define CG_ITERS 20
#define DTf 0.01f
#define KSf 10000.0f
#define CS (BB*NVV)

// ---------------- scratch ----------------------------------------------------
__device__ float    g_pos[3*CS];       // sorted space
__device__ float    g_v0 [3*CS];       // sorted space
__device__ float    g_r  [3*CS];       // sorted space
__device__ float    g_Apb[2][3*CS];    // sorted space
__device__ int      g_cnt[NVV];
__device__ int      g_deg[NVV];        // original space
__device__ int      g_nbr[ELLMAX*NVV];// original space (build)
__device__ int      g_eid[ELLMAX*NVV];// original space (build)
__device__ int      g_perm[NVV];       // sorted pos -> orig vertex
__device__ int      g_ipos[NVV];       // orig vertex -> sorted pos
__device__ unsigned short g_nbr16[ELLMAX*NVV];     // sorted space, u16 positions
__device__ float    g_mass_p[NVV];
__device__ int      g_deg_p[NVV];
__device__ float    g_rest[(size_t)BB*ELLMAX*NVV]; // [b][k][p] sorted space
__device__ float    g_pAp[2][BB][NCTA];
__device__ unsigned g_bar[BB];

// ---------------- helpers ----------------------------------------------------
__device__ __forceinline__ void batch_barrier(unsigned* bar, unsigned target) {
    __syncthreads();
    if (threadIdx.x == 0) {
        asm volatile("red.release.gpu.add.u32 [%0], 1;" :: "l"(bar) : "memory");
        unsigned v;
        do {
            asm volatile("ld.acquire.gpu.u32 %0, [%1];" : "=r"(v) : "l"(bar) : "memory");
        } while (v < target);
    }
    __syncthreads();
}

__device__ __forceinline__ float bred1(float a, float* s16) {
    int lane = threadIdx.x & 31, w = threadIdx.x >> 5;
    #pragma unroll
    for (int o = 16; o; o >>= 1) a += __shfl_down_sync(0xffffffffu, a, o);
    if (lane == 0) s16[w] = a;
    __syncthreads();
    float r = 0.f;
    if (threadIdx.x == 0) {
        #pragma unroll
        for (int k = 0; k < 16; k++) r += s16[k];
    }
    return r;
}

// ---------------- setup -------------------------------------------------------
__global__ void k_zero() {
    int v = blockIdx.x * blockDim.x + threadIdx.x;
    if (v < NVV) g_cnt[v] = 0;
    if (v < BB)  g_bar[v] = 0u;
}

__global__ void k_fill(const int* __restrict__ ei, const int* __restrict__ ej) {
    int e = blockIdx.x * blockDim.x + threadIdx.x;
    if (e >= NEE) return;
    int i = ei[e], j = ej[e];
    int si = atomicAdd(&g_cnt[i], 1);
    if (si < ELLMAX) { g_nbr[si*NVV + i] = j; g_eid[si*NVV + i] = e; }
    int sj = atomicAdd(&g_cnt[j], 1);
    if (sj < ELLMAX) { g_nbr[sj*NVV + j] = i; g_eid[sj*NVV + j] = e; }
}

__global__ void k_sort() {
    int v = blockIdx.x * blockDim.x + threadIdx.x;
    if (v >= NVV) return;
    int d = min(g_cnt[v], ELLMAX);
    g_deg[v] = d;
    long long key[ELLMAX];
    for (int k = 0; k < d; k++)
        key[k] = ((long long)g_nbr[k*NVV + v] << 32) | (unsigned)g_eid[k*NVV + v];
    for (int a = 1; a < d; a++) {
        long long t = key[a]; int c = a - 1;
        while (c >= 0 && key[c] > t) { key[c+1] = key[c]; c--; }
        key[c+1] = t;
    }
    for (int k = 0; k < d; k++) {
        g_nbr[k*NVV + v] = (int)(key[k] >> 32);
        g_eid[k*NVV + v] = (int)(key[k] & 0xffffffffLL);
    }
}

// stable counting sort of vertices by degree (deterministic)
__global__ void k_perm() {
    __shared__ int s_cnt[64], s_off[64];
    int w = threadIdx.x >> 5, l = threadIdx.x & 31;
    #pragma unroll
    for (int pass = 0; pass < 2; pass++) {
        int d = w + pass*32;
        int cnt = 0;
        for (int b0 = 0; b0 < NVV; b0 += 32) {
            int dg = g_deg[b0 + l];
            unsigned m = __ballot_sync(0xffffffffu, dg == d);
            cnt += __popc(m);
        }
        if (l == 0) s_cnt[d] = cnt;
    }
    __syncthreads();
    if (threadIdx.x == 0) {
        int o = 0;
        for (int d = 0; d < 64; d++) { s_off[d] = o; o += s_cnt[d]; }
    }
    __syncthreads();
    #pragma unroll
    for (int pass = 0; pass < 2; pass++) {
        int d = w + pass*32;
        int off = s_off[d];
        for (int b0 = 0; b0 < NVV; b0 += 32) {
            int v = b0 + l;
            int dg = g_deg[v];
            unsigned m = __ballot_sync(0xffffffffu, dg == d);
            if (dg == d) {
                int rank = __popc(m & ((1u << l) - 1u));
                g_perm[off + rank] = v;
                g_ipos[v] = off + rank;
            }
            off += __popc(m);
        }
    }
}

// build sorted-space data: mass, deg, u16 ELL of sorted positions
__global__ void k_sdata(const float* __restrict__ mass) {
    int p = blockIdx.x * blockDim.x + threadIdx.x;
    if (p >= NVV) return;
    int v = g_perm[p];
    g_mass_p[p] = mass[v];
    int d = g_deg[v];
    g_deg_p[p] = d;
    for (int k = 0; k < d; k++)
        g_nbr16[k*NVV + p] = (unsigned short)g_ipos[g_nbr[k*NVV + v]];
}

// permute pos0/vel0 into sorted planar SoA
__global__ void k_init(const float* __restrict__ pos0, const float* __restrict__ vel0) {
    int idx = blockIdx.x * blockDim.x + threadIdx.x;   // idx = b*NVV + p
    if (idx >= CS) return;
    int p = idx & (NVV-1), b = idx >> 13;
    int v = g_perm[p];
    size_t src = ((size_t)b*NVV + v)*3;
    #pragma unroll
    for (int c = 0; c < 3; c++) {
        g_pos[c*CS + idx] = pos0[src + c];
        g_v0 [c*CS + idx] = vel0[src + c];
    }
}

__global__ void k_rest(const float* __restrict__ rest_len, const float* __restrict__ act) {
    int p = blockIdx.x * blockDim.x + threadIdx.x;
    int b = blockIdx.y;
    if (p >= NVV) return;
    int v = g_perm[p];
    int d = g_deg[v];
    for (int k = 0; k < d; k++) {
        int e = g_eid[k*NVV + v];
        g_rest[((size_t)b*ELLMAX + k)*NVV + p] = rest_len[e] * (1.f + act[(size_t)b*NEE + e]);
    }
}

// ---------------- persistent solver -------------------------------------------
__global__ void __launch_bounds__(TPB, 1) k_main(float* __restrict__ out) {
    extern __shared__ float sm[];
    float2* s_pxy = (float2*)sm;          // 64 KB
    float*  s_pz  = sm + 16384;           // 32 KB
    float*  s_rx  = sm + 24576;           // 96 KB
    float*  s_ry  = sm + 32768;
    float*  s_rz  = sm + 40960;
    __shared__ float s16[16];
    __shared__ float s_ab[2];
    __shared__ float s_rs;

    const int tid = threadIdx.x, cx = blockIdx.x, b = blockIdx.y;
    const int w = tid >> 5, l = tid & 31;
    const int base = b*NVV;
    unsigned* bar = &g_bar[b];
    unsigned ph = 0;

    // thread's 4 sorted positions: 4 consecutive chunks (similar degree)
    int pq[VPT], dq[VPT];
    float mmq[VPT];
    float PO[VPT][3], X[VPT][3];
    int dmax = 0;
    #pragma unroll
    for (int q = 0; q < VPT; q++) {
        int c = (w*NCTA + cx)*VPT + q;
        int p = c*32 + l;
        pq[q] = p;
        dq[q] = g_deg_p[p];
        dmax = max(dmax, dq[q]);
        mmq[q] = g_mass_p[p];
        int i = base + p;
        PO[q][0] = g_pos[i]; PO[q][1] = g_pos[CS+i]; PO[q][2] = g_pos[2*CS+i];
        X [q][0] = g_v0[i];  X [q][1] = g_v0[CS+i];  X [q][2] = g_v0[2*CS+i];
    }

    for (int s = 0; s < NSUB; s++) {
        // ---- stage pos ----
        #pragma unroll
        for (int j = 0; j < 16; j++) {
            int p = j*TPB + tid, i = base + p;
            s_pxy[p] = make_float2(__ldcg(&g_pos[i]), __ldcg(&g_pos[CS+i]));
            s_pz [p] = __ldcg(&g_pos[2*CS+i]);
        }
        __syncthreads();

        // ---- force, b = m v + dt f (interleaved q, uniform trip) ----
        float fa[VPT][3];
        #pragma unroll
        for (int q = 0; q < VPT; q++) { fa[q][0] = 0.f; fa[q][1] = 0.f; fa[q][2] = 0.f; }
        for (int k = 0; k < dmax; k++) {
            #pragma unroll
            for (int q = 0; q < VPT; q++) {
                if (k < dq[q]) {
                    int u = g_nbr16[k*NVV + pq[q]];
                    float2 t = s_pxy[u];
                    float dx = PO[q][0] - t.x;
                    float dy = PO[q][1] - t.y;
                    float dz = PO[q][2] - s_pz[u];
                    float len = sqrtf(dx*dx + dy*dy + dz*dz);
                    float rr = g_rest[((size_t)b*ELLMAX + k)*NVV + pq[q]];
                    float cc = -KSf * (len - rr) / fmaxf(len, 1e-6f);
                    fa[q][0] += cc*dx; fa[q][1] += cc*dy; fa[q][2] += cc*dz;
                }
            }
        }
        #pragma unroll
        for (int q = 0; q < VPT; q++) {
            int i = base + pq[q];
            float bx = mmq[q]*X[q][0] + DTf*fa[q][0];
            float by = mmq[q]*X[q][1] + DTf*(fa[q][1] + mmq[q]*(-9.8f));
            float bz = mmq[q]*X[q][2] + DTf*fa[q][2];
            X[q][0] = 0.f; X[q][1] = 0.f; X[q][2] = 0.f;
            __stcg(&g_r[i], bx); __stcg(&g_r[CS+i], by); __stcg(&g_r[2*CS+i], bz);
        }
        batch_barrier(bar, NCTA * (++ph));

        // ---- stage r -> smem (r and p); rs0 locally ----
        float rs_loc = 0.f;
        #pragma unroll
        for (int j = 0; j < 16; j++) {
            int p = j*TPB + tid, i = base + p;
            float rx = __ldcg(&g_r[i]);
            float ry = __ldcg(&g_r[CS+i]);
            float rz = __ldcg(&g_r[2*CS+i]);
            s_rx[p] = rx; s_ry[p] = ry; s_rz[p] = rz;
            s_pxy[p] = make_float2(rx, ry); s_pz[p] = rz;
            rs_loc += rx*rx + ry*ry + rz*rz;
        }
        __syncthreads();
        {
            float t = bred1(rs_loc, s16);
            if (tid == 0) s_rs = t;
        }
        __syncthreads();

        // ---- CG iterations ----
        for (int it = 0; it < CG_ITERS; it++) {
            const int par = it & 1;
            float* Ap = g_Apb[par];

            // matvec (interleaved q) + pAp partial
            float sa[VPT][3];
            #pragma unroll
            for (int q = 0; q < VPT; q++) { sa[q][0] = 0.f; sa[q][1] = 0.f; sa[q][2] = 0.f; }
            for (int k = 0; k < dmax; k++) {
                #pragma unroll
                for (int q = 0; q < VPT; q++) {
                    if (k < dq[q]) {
                        int u = g_nbr16[k*NVV + pq[q]];
                        float2 t = s_pxy[u];
                        sa[q][0] += t.x; sa[q][1] += t.y; sa[q][2] += s_pz[u];
                    }
                }
            }
            float pap = 0.f;
            #pragma unroll
            for (int q = 0; q < VPT; q++) {
                int p = pq[q], i = base + p;
                float2 pv = s_pxy[p]; float pz = s_pz[p];
                float md = mmq[q] + (float)dq[q];
                float ax = md*pv.x - sa[q][0];
                float ay = md*pv.y - sa[q][1];
                float az = md*pz   - sa[q][2];
                __stcg(&Ap[i], ax); __stcg(&Ap[CS+i], ay); __stcg(&Ap[2*CS+i], az);
                pap += pv.x*ax + pv.y*ay + pz*az;
            }
            {
                float t = bred1(pap, s16);
                if (tid == 0) __stcg(&g_pAp[par][b][cx], t);
            }
            batch_barrier(bar, NCTA * (++ph));

            if (tid == 0) {
                float sp = 0.f;
                #pragma unroll
                for (int k = 0; k < NCTA; k++) sp += __ldcg(&g_pAp[par][b][k]);
                s_ab[0] = s_rs / (sp + 1e-12f);
            }
            __syncthreads();
            float alpha = s_ab[0];

            #pragma unroll
            for (int q = 0; q < VPT; q++) {
                int p = pq[q];
                float2 pv = s_pxy[p];
                X[q][0] += alpha*pv.x; X[q][1] += alpha*pv.y; X[q][2] += alpha*s_pz[p];
            }

            if (it < CG_ITERS - 1) {
                float rsn_loc = 0.f;
                #pragma unroll
                for (int j = 0; j < 16; j++) {
                    int p = j*TPB + tid, i = base + p;
                    float rx = s_rx[p] - alpha*__ldcg(&Ap[i]);
                    float ry = s_ry[p] - alpha*__ldcg(&Ap[CS+i]);
                    float rz = s_rz[p] - alpha*__ldcg(&Ap[2*CS+i]);
                    s_rx[p] = rx; s_ry[p] = ry; s_rz[p] = rz;
                    rsn_loc += rx*rx + ry*ry + rz*rz;
                }
                __syncthreads();
                {
                    float t = bred1(rsn_loc, s16);
                    if (tid == 0) { s_ab[1] = t / (s_rs + 1e-12f); s_rs = t; }
                }
                __syncthreads();
                float beta = s_ab[1];
                #pragma unroll
                for (int j = 0; j < 16; j++) {
                    int p = j*TPB + tid;
                    float2 po = s_pxy[p]; float poz = s_pz[p];
                    s_pxy[p] = make_float2(fmaf(beta, po.x, s_rx[p]),
                                           fmaf(beta, po.y, s_ry[p]));
                    s_pz [p] = fmaf(beta, poz, s_rz[p]);
                }
                __syncthreads();
            }
        }

        // ---- pos += dt x ; emit trajectory (scatter via perm) ----
        #pragma unroll
        for (int q = 0; q < VPT; q++) {
            int p = pq[q], i = base + p;
            PO[q][0] += DTf*X[q][0];
            PO[q][1] += DTf*X[q][1];
            PO[q][2] += DTf*X[q][2];
            __stcg(&g_pos[i],      PO[q][0]);
            __stcg(&g_pos[CS+i],   PO[q][1]);
            __stcg(&g_pos[2*CS+i], PO[q][2]);
            int vorig = g_perm[p];
            size_t o = (((size_t)b*NSUB + s)*NVV + vorig)*3;
            out[o+0] = PO[q][0]; out[o+1] = PO[q][1]; out[o+2] = PO[q][2];
        }
        batch_barrier(bar, NCTA * (++ph));
    }
}

// ---------------- launch -------------------------------------------------------
extern "C" void kernel_launch(void* const* d_in, const int* in_sizes, int n_in,
                              void* d_out, int out_size) {
    const float* act   = (const float*)d_in[0];
    const float* pos0  = (const float*)d_in[1];
    const float* vel0  = (const float*)d_in[2];
    const float* rlen  = (const float*)d_in[3];
    const float* mass  = (const float*)d_in[4];
    const int*   ei    = (const int*)d_in[5];
    const int*   ej    = (const int*)d_in[6];
    float*       out   = (float*)d_out;

    const int smbytes = 49152 * sizeof(float);   // 192 KB
    static int attr_done = 0;
    if (!attr_done) {
        cudaFuncSetAttribute(k_main, cudaFuncAttributeMaxDynamicSharedMemorySize, smbytes);
        attr_done = 1;
    }

    k_zero <<<(NVV+255)/256, 256>>>();
    k_fill <<<(NEE+255)/256, 256>>>(ei, ej);
    k_sort <<<(NVV+127)/128, 128>>>();
    k_perm <<<1, 1024>>>();
    k_sdata<<<(NVV+255)/256, 256>>>(mass);
    k_init <<<(CS+255)/256, 256>>>(pos0, vel0);
    k_rest <<<dim3(NVV/256, BB), 256>>>(rlen, act);

    k_main<<<dim3(NCTA, BB), TPB, smbytes>>>(out);
}

// round 8
// speedup vs baseline: 1.1905x; 1.0041x over previous
#include <cuda_runtime.h>

#define BB 32
#define NVV 8192
#define NEE 65536
#define ELLMAX 48
#define NSUB 8
#define NCTA 4          // CTAs per batch (128 total, occ 1, all resident)
#define TPB 1024
#define VPT 2
#define CG_ITERS 20
#define DTf 0.01f
#define KSf 10000.0f
#define CS (BB*NVV)

// ---------------- scratch ----------------------------------------------------
__device__ float    g_pos[3*CS];       // sorted space, planar
__device__ float    g_v0 [3*CS];
__device__ float    g_r  [3*CS];
__device__ float4   g_Ap4[2][CS];      // vectorized Ap, double-buffered
__device__ int      g_cnt[NVV];
__device__ int      g_deg[NVV];
__device__ int      g_nbr[ELLMAX*NVV];
__device__ int      g_eid[ELLMAX*NVV];
__device__ int      g_perm[NVV];
__device__ int      g_ipos[NVV];
__device__ unsigned short g_nbr16[ELLMAX*NVV];
__device__ float    g_mass_p[NVV];
__device__ int      g_deg_p[NVV];
__device__ float    g_rest[(size_t)BB*ELLMAX*NVV];
__device__ float    g_pAp[2][BB][NCTA];
__device__ unsigned g_bar[BB];
__device__ unsigned g_gbar;

// ---------------- helpers ----------------------------------------------------
__device__ __forceinline__ void spin_barrier(unsigned* bar, unsigned target) {
    __syncthreads();
    if (threadIdx.x == 0) {
        asm volatile("red.release.gpu.add.u32 [%0], 1;" :: "l"(bar) : "memory");
        unsigned v;
        do {
            asm volatile("ld.acquire.gpu.u32 %0, [%1];" : "=r"(v) : "l"(bar) : "memory");
        } while (v < target);
    }
    __syncthreads();
}

// reduce over 1024 threads; valid on thread 0
__device__ __forceinline__ float bred1(float a, float* s32) {
    int lane = threadIdx.x & 31, w = threadIdx.x >> 5;
    #pragma unroll
    for (int o = 16; o; o >>= 1) a += __shfl_down_sync(0xffffffffu, a, o);
    if (lane == 0) s32[w] = a;
    __syncthreads();
    float r = 0.f;
    if (threadIdx.x == 0) {
        #pragma unroll
        for (int k = 0; k < 32; k++) r += s32[k];
    }
    return r;
}

// ---------------- launch 0: zero ---------------------------------------------
__global__ void k_pre() {
    int v = blockIdx.x * blockDim.x + threadIdx.x;
    if (v < NVV) g_cnt[v] = 0;
    if (v < BB)  g_bar[v] = 0u;
    if (v == 0)  g_gbar = 0u;
}

// ---------------- launch 1: adjacency fill -----------------------------------
__global__ void k_fill(const int* __restrict__ ei, const int* __restrict__ ej) {
    int e = blockIdx.x * blockDim.x + threadIdx.x;
    if (e >= NEE) return;
    int i = ei[e], j = ej[e];
    int si = atomicAdd(&g_cnt[i], 1);
    if (si < ELLMAX) { g_nbr[si*NVV + i] = j; g_eid[si*NVV + i] = e; }
    int sj = atomicAdd(&g_cnt[j], 1);
    if (sj < ELLMAX) { g_nbr[sj*NVV + j] = i; g_eid[sj*NVV + j] = e; }
}

// ---------------- launch 2: fused setup (grid 32 x 1024, all resident) --------
__global__ void k_setup(const float* __restrict__ mass,
                        const float* __restrict__ pos0, const float* __restrict__ vel0,
                        const float* __restrict__ rest_len, const float* __restrict__ act) {
    const int gtid = blockIdx.x * blockDim.x + threadIdx.x;
    const int nthr = gridDim.x * blockDim.x;   // 32768

    // --- phase 1: per-vertex deterministic adjacency sort ---
    for (int v = gtid; v < NVV; v += nthr) {
        int d = min(g_cnt[v], ELLMAX);
        g_deg[v] = d;
        long long key[ELLMAX];
        for (int k = 0; k < d; k++)
            key[k] = ((long long)g_nbr[k*NVV + v] << 32) | (unsigned)g_eid[k*NVV + v];
        for (int a = 1; a < d; a++) {
            long long t = key[a]; int c = a - 1;
            while (c >= 0 && key[c] > t) { key[c+1] = key[c]; c--; }
            key[c+1] = t;
        }
        for (int k = 0; k < d; k++) {
            g_nbr[k*NVV + v] = (int)(key[k] >> 32);
            g_eid[k*NVV + v] = (int)(key[k] & 0xffffffffLL);
        }
    }
    spin_barrier(&g_gbar, gridDim.x * 1u);

    // --- phase 2: stable counting sort by degree (CTA 0 only) ---
    if (blockIdx.x == 0) {
        __shared__ int s_cnt[64], s_off[64];
        int w = threadIdx.x >> 5, l = threadIdx.x & 31;
        #pragma unroll
        for (int pass = 0; pass < 2; pass++) {
            int d = w + pass*32;
            int cnt = 0;
            for (int b0 = 0; b0 < NVV; b0 += 32) {
                int dg = g_deg[b0 + l];
                unsigned m = __ballot_sync(0xffffffffu, dg == d);
                cnt += __popc(m);
            }
            if (l == 0) s_cnt[d] = cnt;
        }
        __syncthreads();
        if (threadIdx.x == 0) {
            int o = 0;
            for (int d = 0; d < 64; d++) { s_off[d] = o; o += s_cnt[d]; }
        }
        __syncthreads();
        #pragma unroll
        for (int pass = 0; pass < 2; pass++) {
            int d = w + pass*32;
            int off = s_off[d];
            for (int b0 = 0; b0 < NVV; b0 += 32) {
                int v = b0 + l;
                int dg = g_deg[v];
                unsigned m = __ballot_sync(0xffffffffu, dg == d);
                if (dg == d) {
                    int rank = __popc(m & ((1u << l) - 1u));
                    g_perm[off + rank] = v;
                    g_ipos[v] = off + rank;
                }
                off += __popc(m);
            }
        }
    }
    spin_barrier(&g_gbar, gridDim.x * 2u);

    // --- phase 3: sorted-space tables ---
    for (int p = gtid; p < NVV; p += nthr) {
        int v = g_perm[p];
        g_mass_p[p] = mass[v];
        int d = g_deg[v];
        g_deg_p[p] = d;
        for (int k = 0; k < d; k++)
            g_nbr16[k*NVV + p] = (unsigned short)g_ipos[g_nbr[k*NVV + v]];
    }
    // permute pos0/vel0 into sorted planar SoA
    for (int idx = gtid; idx < CS; idx += nthr) {
        int p = idx & (NVV-1), b = idx >> 13;
        int v = g_perm[p];
        size_t src = ((size_t)b*NVV + v)*3;
        #pragma unroll
        for (int c = 0; c < 3; c++) {
            g_pos[c*CS + idx] = pos0[src + c];
            g_v0 [c*CS + idx] = vel0[src + c];
        }
    }
    // rest_eff in sorted ELL order
    for (int idx = gtid; idx < BB*NVV; idx += nthr) {
        int p = idx & (NVV-1), b = idx >> 13;
        int v = g_perm[p];
        int d = g_deg[v];
        for (int k = 0; k < d; k++) {
            int e = g_eid[k*NVV + v];
            g_rest[((size_t)b*ELLMAX + k)*NVV + p] = rest_len[e] * (1.f + act[(size_t)b*NEE + e]);
        }
    }
}

// ---------------- launch 3: persistent solver ---------------------------------
__global__ void __launch_bounds__(TPB, 1) k_main(float* __restrict__ out) {
    extern __shared__ float sm[];
    float2* s_pxy = (float2*)sm;          // 64 KB
    float*  s_pz  = sm + 16384;           // 32 KB
    float*  s_rx  = sm + 24576;           // 3 x 32 KB
    float*  s_ry  = sm + 32768;
    float*  s_rz  = sm + 40960;
    __shared__ float s32[32];
    __shared__ float s_ab[2];
    __shared__ float s_rs;

    const int tid = threadIdx.x, cx = blockIdx.x, b = blockIdx.y;
    const int w = tid >> 5, l = tid & 31;
    const int base = b*NVV;
    unsigned* bar = &g_bar[b];
    unsigned ph = 0;

    int pq[VPT], dq[VPT];
    float mmq[VPT];
    float PO[VPT][3], X[VPT][3];
    #pragma unroll
    for (int q = 0; q < VPT; q++) {
        int c = (w*NCTA + cx)*VPT + q;     // consecutive sorted chunks -> similar degree
        int p = c*32 + l;
        pq[q] = p;
        dq[q] = g_deg_p[p];
        mmq[q] = g_mass_p[p];
        int i = base + p;
        PO[q][0] = g_pos[i]; PO[q][1] = g_pos[CS+i]; PO[q][2] = g_pos[2*CS+i];
        X [q][0] = g_v0[i];  X [q][1] = g_v0[CS+i];  X [q][2] = g_v0[2*CS+i];
    }
    const int dmax = max(dq[0], dq[1]);

    for (int s = 0; s < NSUB; s++) {
        // ---- stage pos ----
        #pragma unroll
        for (int j = 0; j < 8; j++) {
            int p = j*TPB + tid, i = base + p;
            s_pxy[p] = make_float2(__ldcg(&g_pos[i]), __ldcg(&g_pos[CS+i]));
            s_pz [p] = __ldcg(&g_pos[2*CS+i]);
        }
        __syncthreads();

        // ---- force, b = m v + dt f ----
        float fa[VPT][3];
        #pragma unroll
        for (int q = 0; q < VPT; q++) { fa[q][0] = 0.f; fa[q][1] = 0.f; fa[q][2] = 0.f; }
        for (int k = 0; k < dmax; k++) {
            #pragma unroll
            for (int q = 0; q < VPT; q++) {
                if (k < dq[q]) {
                    int u = g_nbr16[k*NVV + pq[q]];
                    float2 t = s_pxy[u];
                    float dx = PO[q][0] - t.x;
                    float dy = PO[q][1] - t.y;
                    float dz = PO[q][2] - s_pz[u];
                    float len = sqrtf(dx*dx + dy*dy + dz*dz);
                    float rr = g_rest[((size_t)b*ELLMAX + k)*NVV + pq[q]];
                    float cc = -KSf * (len - rr) / fmaxf(len, 1e-6f);
                    fa[q][0] += cc*dx; fa[q][1] += cc*dy; fa[q][2] += cc*dz;
                }
            }
        }
        #pragma unroll
        for (int q = 0; q < VPT; q++) {
            int i = base + pq[q];
            float bx = mmq[q]*X[q][0] + DTf*fa[q][0];
            float by = mmq[q]*X[q][1] + DTf*(fa[q][1] + mmq[q]*(-9.8f));
            float bz = mmq[q]*X[q][2] + DTf*fa[q][2];
            X[q][0] = 0.f; X[q][1] = 0.f; X[q][2] = 0.f;
            __stcg(&g_r[i], bx); __stcg(&g_r[CS+i], by); __stcg(&g_r[2*CS+i], bz);
        }
        spin_barrier(bar, NCTA * (++ph));

        // ---- stage r -> smem (r and p); rs0 locally ----
        float rs_loc = 0.f;
        #pragma unroll
        for (int j = 0; j < 8; j++) {
            int p = j*TPB + tid, i = base + p;
            float rx = __ldcg(&g_r[i]);
            float ry = __ldcg(&g_r[CS+i]);
            float rz = __ldcg(&g_r[2*CS+i]);
            s_rx[p] = rx; s_ry[p] = ry; s_rz[p] = rz;
            s_pxy[p] = make_float2(rx, ry); s_pz[p] = rz;
            rs_loc += rx*rx + ry*ry + rz*rz;
        }
        __syncthreads();
        {
            float t = bred1(rs_loc, s32);
            if (tid == 0) s_rs = t;
        }
        __syncthreads();

        // ---- CG iterations (one cross-CTA barrier each) ----
        for (int it = 0; it < CG_ITERS; it++) {
            const int par = it & 1;
            float4* Ap = g_Ap4[par];

            // matvec + pAp partial
            float sa[VPT][3];
            #pragma unroll
            for (int q = 0; q < VPT; q++) { sa[q][0] = 0.f; sa[q][1] = 0.f; sa[q][2] = 0.f; }
            for (int k = 0; k < dmax; k++) {
                #pragma unroll
                for (int q = 0; q < VPT; q++) {
                    if (k < dq[q]) {
                        int u = g_nbr16[k*NVV + pq[q]];
                        float2 t = s_pxy[u];
                        sa[q][0] += t.x; sa[q][1] += t.y; sa[q][2] += s_pz[u];
                    }
                }
            }
            float pap = 0.f;
            #pragma unroll
            for (int q = 0; q < VPT; q++) {
                int p = pq[q], i = base + p;
                float2 pv = s_pxy[p]; float pz = s_pz[p];
                float md = mmq[q] + (float)dq[q];
                float ax = md*pv.x - sa[q][0];
                float ay = md*pv.y - sa[q][1];
                float az = md*pz   - sa[q][2];
                __stcg(&Ap[i], make_float4(ax, ay, az, 0.f));
                pap += pv.x*ax + pv.y*ay + pz*az;
            }
            {
                float t = bred1(pap, s32);
                if (tid == 0) __stcg(&g_pAp[par][b][cx], t);
            }
            spin_barrier(bar, NCTA * (++ph));

            if (tid == 0) {
                float sp = 0.f;
                #pragma unroll
                for (int k = 0; k < NCTA; k++) sp += __ldcg(&g_pAp[par][b][k]);
                s_ab[0] = s_rs / (sp + 1e-12f);
            }
            __syncthreads();
            float alpha = s_ab[0];

            #pragma unroll
            for (int q = 0; q < VPT; q++) {
                int p = pq[q];
                float2 pv = s_pxy[p];
                X[q][0] += alpha*pv.x; X[q][1] += alpha*pv.y; X[q][2] += alpha*s_pz[p];
            }

            if (it < CG_ITERS - 1) {
                // pass 1: r -= alpha Ap ; rs_new (full vector, local)
                float rsn_loc = 0.f;
                #pragma unroll
                for (int j = 0; j < 8; j++) {
                    int p = j*TPB + tid, i = base + p;
                    float4 a4 = __ldcg(&Ap[i]);
                    float rx = s_rx[p] - alpha*a4.x;
                    float ry = s_ry[p] - alpha*a4.y;
                    float rz = s_rz[p] - alpha*a4.z;
                    s_rx[p] = rx; s_ry[p] = ry; s_rz[p] = rz;
                    rsn_loc += rx*rx + ry*ry + rz*rz;
                }
                __syncthreads();
                {
                    float t = bred1(rsn_loc, s32);
                    if (tid == 0) { s_ab[1] = t / (s_rs + 1e-12f); s_rs = t; }
                }
                __syncthreads();
                float beta = s_ab[1];
                // pass 2: p = r + beta p
                #pragma unroll
                for (int j = 0; j < 8; j++) {
                    int p = j*TPB + tid;
                    float2 po = s_pxy[p]; float poz = s_pz[p];
                    s_pxy[p] = make_float2(fmaf(beta, po.x, s_rx[p]),
                                           fmaf(beta, po.y, s_ry[p]));
                    s_pz [p] = fmaf(beta, poz, s_rz[p]);
                }
                __syncthreads();
            }
        }

        // ---- pos += dt x ; emit trajectory ----
        #pragma unroll
        for (int q = 0; q < VPT; q++) {
            int p = pq[q], i = base + p;
            PO[q][0] += DTf*X[q][0];
            PO[q][1] += DTf*X[q][1];
            PO[q][2] += DTf*X[q][2];
            __stcg(&g_pos[i],      PO[q][0]);
            __stcg(&g_pos[CS+i],   PO[q][1]);
            __stcg(&g_pos[2*CS+i], PO[q][2]);
            int vorig = g_perm[p];
            size_t o = (((size_t)b*NSUB + s)*NVV + vorig)*3;
            out[o+0] = PO[q][0]; out[o+1] = PO[q][1]; out[o+2] = PO[q][2];
        }
        spin_barrier(bar, NCTA * (++ph));
    }
}

// ---------------- launch -------------------------------------------------------
extern "C" void kernel_launch(void* const* d_in, const int* in_sizes, int n_in,
                              void* d_out, int out_size) {
    const float* act   = (const float*)d_in[0];
    const float* pos0  = (const float*)d_in[1];
    const float* vel0  = (const float*)d_in[2];
    const float* rlen  = (const float*)d_in[3];
    const float* mass  = (const float*)d_in[4];
    const int*   ei    = (const int*)d_in[5];
    const int*   ej    = (const int*)d_in[6];
    float*       out   = (float*)d_out;

    const int smbytes = 49152 * sizeof(float);   // 192 KB
    static int attr_done = 0;
    if (!attr_done) {
        cudaFuncSetAttribute(k_main, cudaFuncAttributeMaxDynamicSharedMemorySize, smbytes);
        attr_done = 1;
    }

    k_pre  <<<(NVV+255)/256, 256>>>();                       // launch 0
    k_fill <<<(NEE+255)/256, 256>>>(ei, ej);                 // launch 1
    k_setup<<<32, 1024>>>(mass, pos0, vel0, rlen, act);      // launch 2
    k_main <<<dim3(NCTA, BB), TPB, smbytes>>>(out);          // launch 3 (profiled)
}

// round 10
// speedup vs baseline: 1.3587x; 1.1413x over previous
#include <cuda_runtime.h>
#include <cstdint>

#define BB 32
#define NVV 8192
#define NEE 65536
#define ELLMAX 48
#define KPAIR 24        // ELLMAX/2 index pairs
#define NSUB 8
#define NCTA 4          // CTAs per batch = one cluster
#define TPB 1024
#define VPT 2
#define NW 32           // warps per CTA
#define CG_ITERS 20
#define DTf 0.01f
#define KSf 10000.0f
#define CS (BB*NVV)

// ---------------- scratch ----------------------------------------------------
__device__ float    g_pos[3*CS];       // sorted space, planar
__device__ float    g_v0 [3*CS];
__device__ float    g_r  [3*CS];
__device__ float4   g_Ap4[2][CS];      // vectorized Ap, double-buffered
__device__ int      g_cnt[NVV];
__device__ int      g_deg[NVV];
__device__ int      g_nbr[ELLMAX*NVV];
__device__ int      g_eid[ELLMAX*NVV];
__device__ int      g_perm[NVV];
__device__ int      g_ipos[NVV];
__device__ unsigned g_nbrp[KPAIR*NVV]; // packed sorted-position pairs
__device__ float    g_mass_p[NVV];
__device__ int      g_deg_p[NVV];
__device__ float    g_rest[(size_t)BB*ELLMAX*NVV];
__device__ unsigned g_gbar;

// ---------------- helpers ----------------------------------------------------
__device__ __forceinline__ void gpu_spin_barrier(unsigned* bar, unsigned target) {
    __syncthreads();
    if (threadIdx.x == 0) {
        asm volatile("red.release.gpu.add.u32 [%0], 1;" :: "l"(bar) : "memory");
        unsigned v;
        do {
            asm volatile("ld.acquire.gpu.u32 %0, [%1];" : "=r"(v) : "l"(bar) : "memory");
        } while (v < target);
    }
    __syncthreads();
}

#define CLUSTER_SYNC_() do { \
    asm volatile("barrier.cluster.arrive.aligned;" ::: "memory"); \
    asm volatile("barrier.cluster.wait.aligned;"   ::: "memory"); \
} while (0)

__device__ __forceinline__ float dsmem_read_f32(uint32_t saddr, uint32_t rank) {
    uint32_t ra; float v;
    asm volatile("mapa.shared::cluster.u32 %0, %1, %2;" : "=r"(ra) : "r"(saddr), "r"(rank));
    asm volatile("ld.shared::cluster.f32 %0, [%1];" : "=f"(v) : "r"(ra));
    return v;
}

// log-tree reduce over 1024 threads; result valid on thread 0
__device__ __forceinline__ float bredt(float a, float* s32) {
    int lane = threadIdx.x & 31, w = threadIdx.x >> 5;
    #pragma unroll
    for (int o = 16; o; o >>= 1) a += __shfl_down_sync(0xffffffffu, a, o);
    if (lane == 0) s32[w] = a;
    __syncthreads();
    float t = 0.f;
    if (w == 0) {
        t = s32[lane];
        #pragma unroll
        for (int o = 16; o; o >>= 1) t += __shfl_down_sync(0xffffffffu, t, o);
    }
    return t;
}

// ---------------- launch 0: zero ---------------------------------------------
__global__ void k_pre() {
    int v = blockIdx.x * blockDim.x + threadIdx.x;
    if (v < NVV) g_cnt[v] = 0;
    if (v == 0)  g_gbar = 0u;
}

// ---------------- launch 1: adjacency fill -----------------------------------
__global__ void k_fill(const int* __restrict__ ei, const int* __restrict__ ej) {
    int e = blockIdx.x * blockDim.x + threadIdx.x;
    if (e >= NEE) return;
    int i = ei[e], j = ej[e];
    int si = atomicAdd(&g_cnt[i], 1);
    if (si < ELLMAX) { g_nbr[si*NVV + i] = j; g_eid[si*NVV + i] = e; }
    int sj = atomicAdd(&g_cnt[j], 1);
    if (sj < ELLMAX) { g_nbr[sj*NVV + j] = i; g_eid[sj*NVV + j] = e; }
}

// ---------------- launch 2: fused setup ---------------------------------------
__global__ void k_setup(const float* __restrict__ mass,
                        const float* __restrict__ pos0, const float* __restrict__ vel0,
                        const float* __restrict__ rest_len, const float* __restrict__ act) {
    const int gtid = blockIdx.x * blockDim.x + threadIdx.x;
    const int nthr = gridDim.x * blockDim.x;

    // phase 1: deterministic per-vertex adjacency sort
    for (int v = gtid; v < NVV; v += nthr) {
        int d = min(g_cnt[v], ELLMAX);
        g_deg[v] = d;
        long long key[ELLMAX];
        for (int k = 0; k < d; k++)
            key[k] = ((long long)g_nbr[k*NVV + v] << 32) | (unsigned)g_eid[k*NVV + v];
        for (int a = 1; a < d; a++) {
            long long t = key[a]; int c = a - 1;
            while (c >= 0 && key[c] > t) { key[c+1] = key[c]; c--; }
            key[c+1] = t;
        }
        for (int k = 0; k < d; k++) {
            g_nbr[k*NVV + v] = (int)(key[k] >> 32);
            g_eid[k*NVV + v] = (int)(key[k] & 0xffffffffLL);
        }
    }
    gpu_spin_barrier(&g_gbar, gridDim.x * 1u);

    // phase 2: stable counting sort by degree (CTA 0)
    if (blockIdx.x == 0) {
        __shared__ int s_cnt[64], s_off[64];
        int w = threadIdx.x >> 5, l = threadIdx.x & 31;
        #pragma unroll
        for (int pass = 0; pass < 2; pass++) {
            int d = w + pass*32;
            int cnt = 0;
            for (int b0 = 0; b0 < NVV; b0 += 32) {
                int dg = g_deg[b0 + l];
                unsigned m = __ballot_sync(0xffffffffu, dg == d);
                cnt += __popc(m);
            }
            if (l == 0) s_cnt[d] = cnt;
        }
        __syncthreads();
        if (threadIdx.x == 0) {
            int o = 0;
            for (int d = 0; d < 64; d++) { s_off[d] = o; o += s_cnt[d]; }
        }
        __syncthreads();
        #pragma unroll
        for (int pass = 0; pass < 2; pass++) {
            int d = w + pass*32;
            int off = s_off[d];
            for (int b0 = 0; b0 < NVV; b0 += 32) {
                int v = b0 + l;
                int dg = g_deg[v];
                unsigned m = __ballot_sync(0xffffffffu, dg == d);
                if (dg == d) {
                    int rank = __popc(m & ((1u << l) - 1u));
                    g_perm[off + rank] = v;
                    g_ipos[v] = off + rank;
                }
                off += __popc(m);
            }
        }
    }
    gpu_spin_barrier(&g_gbar, gridDim.x * 2u);

    // phase 3: sorted-space tables (packed index pairs)
    for (int p = gtid; p < NVV; p += nthr) {
        int v = g_perm[p];
        g_mass_p[p] = mass[v];
        int d = g_deg[v];
        g_deg_p[p] = d;
        for (int kp = 0; kp < KPAIR; kp++) {
            unsigned lo = (2*kp   < d) ? (unsigned)g_ipos[g_nbr[(2*kp  )*NVV + v]] : 0u;
            unsigned hi = (2*kp+1 < d) ? (unsigned)g_ipos[g_nbr[(2*kp+1)*NVV + v]] : 0u;
            g_nbrp[kp*NVV + p] = lo | (hi << 16);
        }
    }
    for (int idx = gtid; idx < CS; idx += nthr) {
        int p = idx & (NVV-1), b = idx >> 13;
        int v = g_perm[p];
        size_t src = ((size_t)b*NVV + v)*3;
        #pragma unroll
        for (int c = 0; c < 3; c++) {
            g_pos[c*CS + idx] = pos0[src + c];
            g_v0 [c*CS + idx] = vel0[src + c];
        }
    }
    for (int idx = gtid; idx < BB*NVV; idx += nthr) {
        int p = idx & (NVV-1), b = idx >> 13;
        int v = g_perm[p];
        int d = g_deg[v];
        for (int k = 0; k < d; k++) {
            int e = g_eid[k*NVV + v];
            g_rest[((size_t)b*ELLMAX + k)*NVV + p] = rest_len[e] * (1.f + act[(size_t)b*NEE + e]);
        }
    }
}

// ---------------- launch 3: persistent clustered solver ------------------------
__global__ void __launch_bounds__(TPB, 1) __cluster_dims__(NCTA, 1, 1)
k_main(float* __restrict__ out) {
    extern __shared__ float sm[];
    float2* s_pxy = (float2*)sm;          // 64 KB
    float*  s_pz  = sm + 16384;           // 32 KB
    float*  s_rx  = sm + 24576;           // 3 x 32 KB
    float*  s_ry  = sm + 32768;
    float*  s_rz  = sm + 40960;
    __shared__ float s32[32];
    __shared__ float s_ab[2];
    __shared__ float s_rs;
    __shared__ float s_mail[2];           // pAp partial mailbox, parity-buffered

    const int tid = threadIdx.x, cx = blockIdx.x, b = blockIdx.y;
    const int w = tid >> 5, l = tid & 31;
    const int base = b*NVV;

    // balanced ownership: q=0 low-degree half, q=1 high-degree half
    int pq[VPT], dq[VPT];
    float mmq[VPT];
    float PO[VPT][3], X[VPT][3];
    #pragma unroll
    for (int q = 0; q < VPT; q++) {
        int c = q*(NW*NCTA) + w*NCTA + cx;
        int p = c*32 + l;
        pq[q] = p;
        dq[q] = g_deg_p[p];
        mmq[q] = g_mass_p[p];
        int i = base + p;
        PO[q][0] = g_pos[i]; PO[q][1] = g_pos[CS+i]; PO[q][2] = g_pos[2*CS+i];
        X [q][0] = g_v0[i];  X [q][1] = g_v0[CS+i];  X [q][2] = g_v0[2*CS+i];
    }

    for (int s = 0; s < NSUB; s++) {
        // ---- stage pos ----
        #pragma unroll
        for (int j = 0; j < 8; j++) {
            int p = j*TPB + tid, i = base + p;
            s_pxy[p] = make_float2(__ldcg(&g_pos[i]), __ldcg(&g_pos[CS+i]));
            s_pz [p] = __ldcg(&g_pos[2*CS+i]);
        }
        __syncthreads();

        // ---- force, b = m v + dt f -> g_r slice ----
        #pragma unroll
        for (int q = 0; q < VPT; q++) {
            int p = pq[q], i = base + p, d = dq[q];
            int np = (d + 1) >> 1;
            float fx = 0.f, fy = 0.f, fz = 0.f;
            unsigned cur = g_nbrp[p];             // prefetch pair 0
            for (int kp = 0; kp < np; kp++) {
                unsigned nxt = (kp+1 < np) ? g_nbrp[(kp+1)*NVV + p] : 0u;
                int u0 = cur & 0xffffu, u1 = cur >> 16;
                {
                    float2 t = s_pxy[u0];
                    float dx = PO[q][0] - t.x, dy = PO[q][1] - t.y, dz = PO[q][2] - s_pz[u0];
                    float len = sqrtf(dx*dx + dy*dy + dz*dz);
                    float rr = g_rest[((size_t)b*ELLMAX + 2*kp)*NVV + p];
                    float cc = -KSf * (len - rr) / fmaxf(len, 1e-6f);
                    fx += cc*dx; fy += cc*dy; fz += cc*dz;
                }
                if (2*kp + 1 < d) {
                    float2 t = s_pxy[u1];
                    float dx = PO[q][0] - t.x, dy = PO[q][1] - t.y, dz = PO[q][2] - s_pz[u1];
                    float len = sqrtf(dx*dx + dy*dy + dz*dz);
                    float rr = g_rest[((size_t)b*ELLMAX + 2*kp+1)*NVV + p];
                    float cc = -KSf * (len - rr) / fmaxf(len, 1e-6f);
                    fx += cc*dx; fy += cc*dy; fz += cc*dz;
                }
                cur = nxt;
            }
            float bx = mmq[q]*X[q][0] + DTf*fx;
            float by = mmq[q]*X[q][1] + DTf*(fy + mmq[q]*(-9.8f));
            float bz = mmq[q]*X[q][2] + DTf*fz;
            X[q][0] = 0.f; X[q][1] = 0.f; X[q][2] = 0.f;
            __stcg(&g_r[i], bx); __stcg(&g_r[CS+i], by); __stcg(&g_r[2*CS+i], bz);
        }
        CLUSTER_SYNC_();

        // ---- stage r -> smem (r and p); rs0 locally ----
        float rs_loc = 0.f;
        #pragma unroll
        for (int j = 0; j < 8; j++) {
            int p = j*TPB + tid, i = base + p;
            float rx = __ldcg(&g_r[i]);
            float ry = __ldcg(&g_r[CS+i]);
            float rz = __ldcg(&g_r[2*CS+i]);
            s_rx[p] = rx; s_ry[p] = ry; s_rz[p] = rz;
            s_pxy[p] = make_float2(rx, ry); s_pz[p] = rz;
            rs_loc += rx*rx + ry*ry + rz*rz;
        }
        __syncthreads();
        {
            float t = bredt(rs_loc, s32);
            if (tid == 0) s_rs = t;
        }
        __syncthreads();

        // ---- CG iterations ----
        for (int it = 0; it < CG_ITERS; it++) {
            const int par = it & 1;
            float4* Ap = g_Ap4[par];

            // matvec (prefetched pair indices) + pAp partial
            float pap = 0.f;
            #pragma unroll
            for (int q = 0; q < VPT; q++) {
                int p = pq[q], i = base + p, d = dq[q];
                int np = (d + 1) >> 1;
                float sx = 0.f, sy = 0.f, sz = 0.f;
                unsigned cur = g_nbrp[p];
                for (int kp = 0; kp < np; kp++) {
                    unsigned nxt = (kp+1 < np) ? g_nbrp[(kp+1)*NVV + p] : 0u;
                    int u0 = cur & 0xffffu, u1 = cur >> 16;
                    float2 t0 = s_pxy[u0];
                    sx += t0.x; sy += t0.y; sz += s_pz[u0];
                    if (2*kp + 1 < d) {
                        float2 t1 = s_pxy[u1];
                        sx += t1.x; sy += t1.y; sz += s_pz[u1];
                    }
                    cur = nxt;
                }
                float2 pv = s_pxy[p]; float pz = s_pz[p];
                float md = mmq[q] + (float)d;
                float ax = md*pv.x - sx;
                float ay = md*pv.y - sy;
                float az = md*pz   - sz;
                __stcg(&Ap[i], make_float4(ax, ay, az, 0.f));
                pap += pv.x*ax + pv.y*ay + pz*az;
            }
            {
                float t = bredt(pap, s32);
                if (tid == 0) s_mail[par] = t;
            }
            CLUSTER_SYNC_();                     // publishes s_mail + Ap slices

            if (tid == 0) {
                uint32_t ma = (uint32_t)__cvta_generic_to_shared(&s_mail[par]);
                float sp = 0.f;
                #pragma unroll
                for (int rk = 0; rk < NCTA; rk++) sp += dsmem_read_f32(ma, (uint32_t)rk);
                s_ab[0] = s_rs / (sp + 1e-12f);
            }
            __syncthreads();
            float alpha = s_ab[0];

            // x += alpha p (own slice)
            #pragma unroll
            for (int q = 0; q < VPT; q++) {
                int p = pq[q];
                float2 pv = s_pxy[p];
                X[q][0] += alpha*pv.x; X[q][1] += alpha*pv.y; X[q][2] += alpha*s_pz[p];
            }

            if (it < CG_ITERS - 1) {
                // sweep1: r -= alpha Ap (full vector, smem); rs_new from stored r
                float rsn_loc = 0.f;
                #pragma unroll
                for (int j = 0; j < 8; j++) {
                    int p = j*TPB + tid, i = base + p;
                    float4 a4 = __ldcg(&Ap[i]);
                    float rx = s_rx[p] - alpha*a4.x;
                    float ry = s_ry[p] - alpha*a4.y;
                    float rz = s_rz[p] - alpha*a4.z;
                    s_rx[p] = rx; s_ry[p] = ry; s_rz[p] = rz;
                    rsn_loc += rx*rx + ry*ry + rz*rz;
                }
                __syncthreads();
                {
                    float t = bredt(rsn_loc, s32);
                    if (tid == 0) { s_ab[1] = t / (s_rs + 1e-12f); s_rs = t; }
                }
                __syncthreads();
                float beta = s_ab[1];
                // sweep2: p = r + beta p
                #pragma unroll
                for (int j = 0; j < 8; j++) {
                    int p = j*TPB + tid;
                    float2 po = s_pxy[p]; float poz = s_pz[p];
                    s_pxy[p] = make_float2(fmaf(beta, po.x, s_rx[p]),
                                           fmaf(beta, po.y, s_ry[p]));
                    s_pz [p] = fmaf(beta, poz, s_rz[p]);
                }
                __syncthreads();
            }
        }

        // ---- pos += dt x ; emit trajectory ----
        #pragma unroll
        for (int q = 0; q < VPT; q++) {
            int p = pq[q], i = base + p;
            PO[q][0] += DTf*X[q][0];
            PO[q][1] += DTf*X[q][1];
            PO[q][2] += DTf*X[q][2];
            __stcg(&g_pos[i],      PO[q][0]);
            __stcg(&g_pos[CS+i],   PO[q][1]);
            __stcg(&g_pos[2*CS+i], PO[q][2]);
            int vorig = g_perm[p];
            size_t o = (((size_t)b*NSUB + s)*NVV + vorig)*3;
            out[o+0] = PO[q][0]; out[o+1] = PO[q][1]; out[o+2] = PO[q][2];
        }
        CLUSTER_SYNC_();
    }
}

// ---------------- launch -------------------------------------------------------
extern "C" void kernel_launch(void* const* d_in, const int* in_sizes, int n_in,
                              void* d_out, int out_size) {
    const float* act   = (const float*)d_in[0];
    const float* pos0  = (const float*)d_in[1];
    const float* vel0  = (const float*)d_in[2];
    const float* rlen  = (const float*)d_in[3];
    const float* mass  = (const float*)d_in[4];
    const int*   ei    = (const int*)d_in[5];
    const int*   ej    = (const int*)d_in[6];
    float*       out   = (float*)d_out;

    const int smbytes = 49152 * sizeof(float);   // 192 KB
    static int attr_done = 0;
    if (!attr_done) {
        cudaFuncSetAttribute(k_main, cudaFuncAttributeMaxDynamicSharedMemorySize, smbytes);
        attr_done = 1;
    }

    k_pre  <<<(NVV+255)/256, 256>>>();
    k_fill <<<(NEE+255)/256, 256>>>(ei, ej);
    k_setup<<<32, 1024>>>(mass, pos0, vel0, rlen, act);
    k_main <<<dim3(NCTA, BB), TPB, smbytes>>>(out);
}

// round 11
// speedup vs baseline: 1.3606x; 1.0014x over previous
#include <cuda_runtime.h>
#include <cstdint>

#define BB 32
#define NVV 8192
#define NEE 65536
#define ELLMAX 48
#define KPAIR 24        // ELLMAX/2 index pairs
#define NSUB 8
#define NCTA 4          // CTAs per batch = one cluster
#define TPB 1024
#define VPT 2
#define NW 32           // warps per CTA
#define CG_ITERS 20
#define DTf 0.01f
#define KSf 10000.0f
#define CS (BB*NVV)

// ---------------- scratch ----------------------------------------------------
__device__ float    g_pos[3*CS];       // sorted space, planar
__device__ float    g_v0 [3*CS];
__device__ float    g_r  [3*CS];
__device__ float4   g_Ap4[2][CS];      // vectorized Ap, double-buffered
__device__ int      g_cnt[NVV];
__device__ int      g_deg[NVV];
__device__ int      g_nbr[ELLMAX*NVV];
__device__ int      g_eid[ELLMAX*NVV];
__device__ int      g_perm[NVV];
__device__ int      g_ipos[NVV];
__device__ unsigned g_nbrp[KPAIR*NVV]; // packed sorted-position pairs (bank-scheduled)
__device__ int      g_eid_p[ELLMAX*NVV];// edge ids in bank-scheduled sorted-space order
__device__ float    g_mass_p[NVV];
__device__ int      g_deg_p[NVV];
__device__ float    g_rest[(size_t)BB*ELLMAX*NVV];
__device__ unsigned g_gbar;

// ---------------- helpers ----------------------------------------------------
__device__ __forceinline__ void gpu_spin_barrier(unsigned* bar, unsigned target) {
    __syncthreads();
    if (threadIdx.x == 0) {
        asm volatile("red.release.gpu.add.u32 [%0], 1;" :: "l"(bar) : "memory");
        unsigned v;
        do {
            asm volatile("ld.acquire.gpu.u32 %0, [%1];" : "=r"(v) : "l"(bar) : "memory");
        } while (v < target);
    }
    __syncthreads();
}

#define CLUSTER_SYNC_() do { \
    asm volatile("barrier.cluster.arrive.aligned;" ::: "memory"); \
    asm volatile("barrier.cluster.wait.aligned;"   ::: "memory"); \
} while (0)

__device__ __forceinline__ float dsmem_read_f32(uint32_t saddr, uint32_t rank) {
    uint32_t ra; float v;
    asm volatile("mapa.shared::cluster.u32 %0, %1, %2;" : "=r"(ra) : "r"(saddr), "r"(rank));
    asm volatile("ld.shared::cluster.f32 %0, [%1];" : "=f"(v) : "r"(ra));
    return v;
}

// log-tree reduce over 1024 threads; result valid on thread 0
__device__ __forceinline__ float bredt(float a, float* s32) {
    int lane = threadIdx.x & 31, w = threadIdx.x >> 5;
    #pragma unroll
    for (int o = 16; o; o >>= 1) a += __shfl_down_sync(0xffffffffu, a, o);
    if (lane == 0) s32[w] = a;
    __syncthreads();
    float t = 0.f;
    if (w == 0) {
        t = s32[lane];
        #pragma unroll
        for (int o = 16; o; o >>= 1) t += __shfl_down_sync(0xffffffffu, t, o);
    }
    return t;
}

// ---------------- launch 0: zero ---------------------------------------------
__global__ void k_pre() {
    int v = blockIdx.x * blockDim.x + threadIdx.x;
    if (v < NVV) g_cnt[v] = 0;
    if (v == 0)  g_gbar = 0u;
}

// ---------------- launch 1: adjacency fill -----------------------------------
__global__ void k_fill(const int* __restrict__ ei, const int* __restrict__ ej) {
    int e = blockIdx.x * blockDim.x + threadIdx.x;
    if (e >= NEE) return;
    int i = ei[e], j = ej[e];
    int si = atomicAdd(&g_cnt[i], 1);
    if (si < ELLMAX) { g_nbr[si*NVV + i] = j; g_eid[si*NVV + i] = e; }
    int sj = atomicAdd(&g_cnt[j], 1);
    if (sj < ELLMAX) { g_nbr[sj*NVV + j] = i; g_eid[sj*NVV + j] = e; }
}

// ---------------- launch 2: fused setup ---------------------------------------
__global__ void k_setup(const float* __restrict__ mass,
                        const float* __restrict__ pos0, const float* __restrict__ vel0,
                        const float* __restrict__ rest_len, const float* __restrict__ act) {
    const int gtid = blockIdx.x * blockDim.x + threadIdx.x;
    const int nthr = gridDim.x * blockDim.x;

    // phase 1: deterministic per-vertex adjacency sort (canonical base order)
    for (int v = gtid; v < NVV; v += nthr) {
        int d = min(g_cnt[v], ELLMAX);
        g_deg[v] = d;
        long long key[ELLMAX];
        for (int k = 0; k < d; k++)
            key[k] = ((long long)g_nbr[k*NVV + v] << 32) | (unsigned)g_eid[k*NVV + v];
        for (int a = 1; a < d; a++) {
            long long t = key[a]; int c = a - 1;
            while (c >= 0 && key[c] > t) { key[c+1] = key[c]; c--; }
            key[c+1] = t;
        }
        for (int k = 0; k < d; k++) {
            g_nbr[k*NVV + v] = (int)(key[k] >> 32);
            g_eid[k*NVV + v] = (int)(key[k] & 0xffffffffLL);
        }
    }
    gpu_spin_barrier(&g_gbar, gridDim.x * 1u);

    // phase 2: stable counting sort by degree (CTA 0)
    if (blockIdx.x == 0) {
        __shared__ int s_cnt[64], s_off[64];
        int w = threadIdx.x >> 5, l = threadIdx.x & 31;
        #pragma unroll
        for (int pass = 0; pass < 2; pass++) {
            int d = w + pass*32;
            int cnt = 0;
            for (int b0 = 0; b0 < NVV; b0 += 32) {
                int dg = g_deg[b0 + l];
                unsigned m = __ballot_sync(0xffffffffu, dg == d);
                cnt += __popc(m);
            }
            if (l == 0) s_cnt[d] = cnt;
        }
        __syncthreads();
        if (threadIdx.x == 0) {
            int o = 0;
            for (int d = 0; d < 64; d++) { s_off[d] = o; o += s_cnt[d]; }
        }
        __syncthreads();
        #pragma unroll
        for (int pass = 0; pass < 2; pass++) {
            int d = w + pass*32;
            int off = s_off[d];
            for (int b0 = 0; b0 < NVV; b0 += 32) {
                int v = b0 + l;
                int dg = g_deg[v];
                unsigned m = __ballot_sync(0xffffffffu, dg == d);
                if (dg == d) {
                    int rank = __popc(m & ((1u << l) - 1u));
                    g_perm[off + rank] = v;
                    g_ipos[v] = off + rank;
                }
                off += __popc(m);
            }
        }
    }
    gpu_spin_barrier(&g_gbar, gridDim.x * 2u);

    // phase 3: bank-scheduled sorted-space tables.
    // For each sorted position p (gather lane = p & 31):
    //   1. map neighbors to sorted positions,
    //   2. stable-sort the list by smem bank (u & 31),
    //   3. rotate by the lane's quantile offset rot = (lane * d) / 32,
    // so at gather step k the 32 lanes of a warp sample the bank ring at
    // evenly spaced offsets -> near conflict-free crossbar phases.
    for (int p = gtid; p < NVV; p += nthr) {
        int v = g_perm[p];
        g_mass_p[p] = mass[v];
        int d = g_deg[v];
        g_deg_p[p] = d;

        int ulist[ELLMAX], elist[ELLMAX];
        for (int k = 0; k < d; k++) {
            ulist[k] = g_ipos[g_nbr[k*NVV + v]];
            elist[k] = g_eid[k*NVV + v];
        }
        // stable insertion sort by bank (u & 31); ties keep canonical order
        for (int a = 1; a < d; a++) {
            int ut = ulist[a], et = elist[a], kt = ut & 31;
            int c = a - 1;
            while (c >= 0 && (ulist[c] & 31) > kt) {
                ulist[c+1] = ulist[c]; elist[c+1] = elist[c]; c--;
            }
            ulist[c+1] = ut; elist[c+1] = et;
        }
        // rotate by lane quantile
        int lane = p & 31;
        int rot = (d > 0) ? ((lane * d) >> 5) : 0;
        int u2[ELLMAX], e2[ELLMAX];
        for (int k = 0; k < d; k++) {
            int src = k + rot; if (src >= d) src -= d;
            u2[k] = ulist[src]; e2[k] = elist[src];
        }
        for (int kp = 0; kp < KPAIR; kp++) {
            unsigned lo = (2*kp   < d) ? (unsigned)u2[2*kp]   : 0u;
            unsigned hi = (2*kp+1 < d) ? (unsigned)u2[2*kp+1] : 0u;
            g_nbrp[kp*NVV + p] = lo | (hi << 16);
        }
        for (int k = 0; k < d; k++) g_eid_p[k*NVV + p] = e2[k];
    }
    gpu_spin_barrier(&g_gbar, gridDim.x * 3u);

    for (int idx = gtid; idx < CS; idx += nthr) {
        int p = idx & (NVV-1), b = idx >> 13;
        int v = g_perm[p];
        size_t src = ((size_t)b*NVV + v)*3;
        #pragma unroll
        for (int c = 0; c < 3; c++) {
            g_pos[c*CS + idx] = pos0[src + c];
            g_v0 [c*CS + idx] = vel0[src + c];
        }
    }
    // rest_eff in the SAME bank-scheduled order as g_nbrp
    for (int idx = gtid; idx < BB*NVV; idx += nthr) {
        int p = idx & (NVV-1), b = idx >> 13;
        int d = g_deg_p[p];
        for (int k = 0; k < d; k++) {
            int e = g_eid_p[k*NVV + p];
            g_rest[((size_t)b*ELLMAX + k)*NVV + p] = rest_len[e] * (1.f + act[(size_t)b*NEE + e]);
        }
    }
}

// ---------------- launch 3: persistent clustered solver ------------------------
__global__ void __launch_bounds__(TPB, 1) __cluster_dims__(NCTA, 1, 1)
k_main(float* __restrict__ out) {
    extern __shared__ float sm[];
    float2* s_pxy = (float2*)sm;          // 64 KB
    float*  s_pz  = sm + 16384;           // 32 KB
    float*  s_rx  = sm + 24576;           // 3 x 32 KB
    float*  s_ry  = sm + 32768;
    float*  s_rz  = sm + 40960;
    __shared__ float s32[32];
    __shared__ float s_ab[2];
    __shared__ float s_rs;
    __shared__ float s_mail[2];           // pAp partial mailbox, parity-buffered

    const int tid = threadIdx.x, cx = blockIdx.x, b = blockIdx.y;
    const int w = tid >> 5, l = tid & 31;
    const int base = b*NVV;

    // balanced ownership: q=0 low-degree half, q=1 high-degree half
    int pq[VPT], dq[VPT];
    float mmq[VPT];
    float PO[VPT][3], X[VPT][3];
    #pragma unroll
    for (int q = 0; q < VPT; q++) {
        int c = q*(NW*NCTA) + w*NCTA + cx;
        int p = c*32 + l;
        pq[q] = p;
        dq[q] = g_deg_p[p];
        mmq[q] = g_mass_p[p];
        int i = base + p;
        PO[q][0] = g_pos[i]; PO[q][1] = g_pos[CS+i]; PO[q][2] = g_pos[2*CS+i];
        X [q][0] = g_v0[i];  X [q][1] = g_v0[CS+i];  X [q][2] = g_v0[2*CS+i];
    }

    for (int s = 0; s < NSUB; s++) {
        // ---- stage pos ----
        #pragma unroll
        for (int j = 0; j < 8; j++) {
            int p = j*TPB + tid, i = base + p;
            s_pxy[p] = make_float2(__ldcg(&g_pos[i]), __ldcg(&g_pos[CS+i]));
            s_pz [p] = __ldcg(&g_pos[2*CS+i]);
        }
        __syncthreads();

        // ---- force, b = m v + dt f -> g_r slice ----
        #pragma unroll
        for (int q = 0; q < VPT; q++) {
            int p = pq[q], i = base + p, d = dq[q];
            int np = (d + 1) >> 1;
            float fx = 0.f, fy = 0.f, fz = 0.f;
            unsigned cur = g_nbrp[p];             // prefetch pair 0
            for (int kp = 0; kp < np; kp++) {
                unsigned nxt = (kp+1 < np) ? g_nbrp[(kp+1)*NVV + p] : 0u;
                int u0 = cur & 0xffffu, u1 = cur >> 16;
                {
                    float2 t = s_pxy[u0];
                    float dx = PO[q][0] - t.x, dy = PO[q][1] - t.y, dz = PO[q][2] - s_pz[u0];
                    float len = sqrtf(dx*dx + dy*dy + dz*dz);
                    float rr = g_rest[((size_t)b*ELLMAX + 2*kp)*NVV + p];
                    float cc = -KSf * (len - rr) / fmaxf(len, 1e-6f);
                    fx += cc*dx; fy += cc*dy; fz += cc*dz;
                }
                if (2*kp + 1 < d) {
                    float2 t = s_pxy[u1];
                    float dx = PO[q][0] - t.x, dy = PO[q][1] - t.y, dz = PO[q][2] - s_pz[u1];
                    float len = sqrtf(dx*dx + dy*dy + dz*dz);
                    float rr = g_rest[((size_t)b*ELLMAX + 2*kp+1)*NVV + p];
                    float cc = -KSf * (len - rr) / fmaxf(len, 1e-6f);
                    fx += cc*dx; fy += cc*dy; fz += cc*dz;
                }
                cur = nxt;
            }
            float bx = mmq[q]*X[q][0] + DTf*fx;
            float by = mmq[q]*X[q][1] + DTf*(fy + mmq[q]*(-9.8f));
            float bz = mmq[q]*X[q][2] + DTf*fz;
            X[q][0] = 0.f; X[q][1] = 0.f; X[q][2] = 0.f;
            __stcg(&g_r[i], bx); __stcg(&g_r[CS+i], by); __stcg(&g_r[2*CS+i], bz);
        }
        CLUSTER_SYNC_();

        // ---- stage r -> smem (r and p); rs0 locally ----
        float rs_loc = 0.f;
        #pragma unroll
        for (int j = 0; j < 8; j++) {
            int p = j*TPB + tid, i = base + p;
            float rx = __ldcg(&g_r[i]);
            float ry = __ldcg(&g_r[CS+i]);
            float rz = __ldcg(&g_r[2*CS+i]);
            s_rx[p] = rx; s_ry[p] = ry; s_rz[p] = rz;
            s_pxy[p] = make_float2(rx, ry); s_pz[p] = rz;
            rs_loc += rx*rx + ry*ry + rz*rz;
        }
        __syncthreads();
        {
            float t = bredt(rs_loc, s32);
            if (tid == 0) s_rs = t;
        }
        __syncthreads();

        // ---- CG iterations ----
        for (int it = 0; it < CG_ITERS; it++) {
            const int par = it & 1;
            float4* Ap = g_Ap4[par];

            // matvec (prefetched, bank-scheduled pairs) + pAp partial
            float pap = 0.f;
            #pragma unroll
            for (int q = 0; q < VPT; q++) {
                int p = pq[q], i = base + p, d = dq[q];
                int np = (d + 1) >> 1;
                float sx = 0.f, sy = 0.f, sz = 0.f;
                unsigned cur = g_nbrp[p];
                for (int kp = 0; kp < np; kp++) {
                    unsigned nxt = (kp+1 < np) ? g_nbrp[(kp+1)*NVV + p] : 0u;
                    int u0 = cur & 0xffffu, u1 = cur >> 16;
                    float2 t0 = s_pxy[u0];
                    sx += t0.x; sy += t0.y; sz += s_pz[u0];
                    if (2*kp + 1 < d) {
                        float2 t1 = s_pxy[u1];
                        sx += t1.x; sy += t1.y; sz += s_pz[u1];
                    }
                    cur = nxt;
                }
                float2 pv = s_pxy[p]; float pz = s_pz[p];
                float md = mmq[q] + (float)d;
                float ax = md*pv.x - sx;
                float ay = md*pv.y - sy;
                float az = md*pz   - sz;
                __stcg(&Ap[i], make_float4(ax, ay, az, 0.f));
                pap += pv.x*ax + pv.y*ay + pz*az;
            }
            {
                float t = bredt(pap, s32);
                if (tid == 0) s_mail[par] = t;
            }
            CLUSTER_SYNC_();                     // publishes s_mail + Ap slices

            if (tid == 0) {
                uint32_t ma = (uint32_t)__cvta_generic_to_shared(&s_mail[par]);
                float sp = 0.f;
                #pragma unroll
                for (int rk = 0; rk < NCTA; rk++) sp += dsmem_read_f32(ma, (uint32_t)rk);
                s_ab[0] = s_rs / (sp + 1e-12f);
            }
            __syncthreads();
            float alpha = s_ab[0];

            // x += alpha p (own slice)
            #pragma unroll
            for (int q = 0; q < VPT; q++) {
                int p = pq[q];
                float2 pv = s_pxy[p];
                X[q][0] += alpha*pv.x; X[q][1] += alpha*pv.y; X[q][2] += alpha*s_pz[p];
            }

            if (it < CG_ITERS - 1) {
                // sweep1: r -= alpha Ap (full vector, smem); rs_new from stored r
                float rsn_loc = 0.f;
                #pragma unroll
                for (int j = 0; j < 8; j++) {
                    int p = j*TPB + tid, i = base + p;
                    float4 a4 = __ldcg(&Ap[i]);
                    float rx = s_rx[p] - alpha*a4.x;
                    float ry = s_ry[p] - alpha*a4.y;
                    float rz = s_rz[p] - alpha*a4.z;
                    s_rx[p] = rx; s_ry[p] = ry; s_rz[p] = rz;
                    rsn_loc += rx*rx + ry*ry + rz*rz;
                }
                __syncthreads();
                {
                    float t = bredt(rsn_loc, s32);
                    if (tid == 0) { s_ab[1] = t / (s_rs + 1e-12f); s_rs = t; }
                }
                __syncthreads();
                float beta = s_ab[1];
                // sweep2: p = r + beta p
                #pragma unroll
                for (int j = 0; j < 8; j++) {
                    int p = j*TPB + tid;
                    float2 po = s_pxy[p]; float poz = s_pz[p];
                    s_pxy[p] = make_float2(fmaf(beta, po.x, s_rx[p]),
                                           fmaf(beta, po.y, s_ry[p]));
                    s_pz [p] = fmaf(beta, poz, s_rz[p]);
                }
                __syncthreads();
            }
        }

        // ---- pos += dt x ; emit trajectory ----
        #pragma unroll
        for (int q = 0; q < VPT; q++) {
            int p = pq[q], i = base + p;
            PO[q][0] += DTf*X[q][0];
            PO[q][1] += DTf*X[q][1];
            PO[q][2] += DTf*X[q][2];
            __stcg(&g_pos[i],      PO[q][0]);
            __stcg(&g_pos[CS+i],   PO[q][1]);
            __stcg(&g_pos[2*CS+i], PO[q][2]);
            int vorig = g_perm[p];
            size_t o = (((size_t)b*NSUB + s)*NVV + vorig)*3;
            out[o+0] = PO[q][0]; out[o+1] = PO[q][1]; out[o+2] = PO[q][2];
        }
        CLUSTER_SYNC_();
    }
}

// ---------------- launch -------------------------------------------------------
extern "C" void kernel_launch(void* const* d_in, const int* in_sizes, int n_in,
                              void* d_out, int out_size) {
    const float* act   = (const float*)d_in[0];
    const float* pos0  = (const float*)d_in[1];
    const float* vel0  = (const float*)d_in[2];
    const float* rlen  = (const float*)d_in[3];
    const float* mass  = (const float*)d_in[4];
    const int*   ei    = (const int*)d_in[5];
    const int*   ej    = (const int*)d_in[6];
    float*       out   = (float*)d_out;

    const int smbytes = 49152 * sizeof(float);   // 192 KB
    static int attr_done = 0;
    if (!attr_done) {
        cudaFuncSetAttribute(k_main, cudaFuncAttributeMaxDynamicSharedMemorySize, smbytes);
        attr_done = 1;
    }

    k_pre  <<<(NVV+255)/256, 256>>>();
    k_fill <<<(NEE+255)/256, 256>>>(ei, ej);
    k_setup<<<32, 1024>>>(mass, pos0, vel0, rlen, act);
    k_main <<<dim3(NCTA, BB), TPB, smbytes>>>(out);
}

// round 13
// speedup vs baseline: 1.3832x; 1.0166x over previous
#include <cuda_runtime.h>
#include <cstdint>

#define BB 32
#define NVV 8192
#define NEE 65536
#define ELLMAX 48
#define KPAIR 24        // ELLMAX/2 index pairs
#define NSUB 8
#define NCTA 4          // CTAs per batch = one cluster
#define TPB 512
#define VPT 4           // gather vertices per thread
#define NCH 16          // r chunks per thread (NVV/TPB)
#define NW 16           // warps per CTA
#define CG_ITERS 20
#define DTf 0.01f
#define KSf 10000.0f
#define CS (BB*NVV)
#define NVP 8208        // NVV + 16 sentinel slots for smem p arrays

// ---------------- scratch ----------------------------------------------------
__device__ float    g_pos[3*CS];       // sorted space, planar
__device__ float    g_v0 [3*CS];
__device__ float    g_r  [3*CS];
__device__ float4   g_Ap4[2][CS];      // vectorized Ap, double-buffered
__device__ int      g_cnt[NVV];
__device__ int      g_deg[NVV];
__device__ int      g_nbr[ELLMAX*NVV];
__device__ int      g_eid[ELLMAX*NVV];
__device__ int      g_perm[NVV];
__device__ int      g_ipos[NVV];
__device__ unsigned g_nbrp[KPAIR*NVV]; // packed sorted-position pairs (sentinel-padded)
__device__ float    g_mass_p[NVV];
__device__ int      g_deg_p[NVV];
__device__ float    g_rest[(size_t)BB*ELLMAX*NVV];
__device__ unsigned g_gbar;

// ---------------- helpers ----------------------------------------------------
__device__ __forceinline__ void gpu_spin_barrier(unsigned* bar, unsigned target) {
    __syncthreads();
    if (threadIdx.x == 0) {
        asm volatile("red.release.gpu.add.u32 [%0], 1;" :: "l"(bar) : "memory");
        unsigned v;
        do {
            asm volatile("ld.acquire.gpu.u32 %0, [%1];" : "=r"(v) : "l"(bar) : "memory");
        } while (v < target);
    }
    __syncthreads();
}

#define CLUSTER_SYNC_() do { \
    asm volatile("barrier.cluster.arrive.aligned;" ::: "memory"); \
    asm volatile("barrier.cluster.wait.aligned;"   ::: "memory"); \
} while (0)

__device__ __forceinline__ float dsmem_read_f32(uint32_t saddr, uint32_t rank) {
    uint32_t ra; float v;
    asm volatile("mapa.shared::cluster.u32 %0, %1, %2;" : "=r"(ra) : "r"(saddr), "r"(rank));
    asm volatile("ld.shared::cluster.f32 %0, [%1];" : "=f"(v) : "r"(ra));
    return v;
}

// log-tree reduce over 512 threads (16 warps); result valid on thread 0
__device__ __forceinline__ float bredt(float a, float* s16) {
    int lane = threadIdx.x & 31, w = threadIdx.x >> 5;
    #pragma unroll
    for (int o = 16; o; o >>= 1) a += __shfl_down_sync(0xffffffffu, a, o);
    if (lane == 0) s16[w] = a;
    __syncthreads();
    float t = 0.f;
    if (w == 0) {
        t = (lane < NW) ? s16[lane] : 0.f;
        #pragma unroll
        for (int o = 8; o; o >>= 1) t += __shfl_down_sync(0xffffffffu, t, o);
    }
    return t;
}

// ---------------- launch 0: zero ---------------------------------------------
__global__ void k_pre() {
    int v = blockIdx.x * blockDim.x + threadIdx.x;
    if (v < NVV) g_cnt[v] = 0;
    if (v == 0)  g_gbar = 0u;
}

// ---------------- launch 1: adjacency fill -----------------------------------
__global__ void k_fill(const int* __restrict__ ei, const int* __restrict__ ej) {
    int e = blockIdx.x * blockDim.x + threadIdx.x;
    if (e >= NEE) return;
    int i = ei[e], j = ej[e];
    int si = atomicAdd(&g_cnt[i], 1);
    if (si < ELLMAX) { g_nbr[si*NVV + i] = j; g_eid[si*NVV + i] = e; }
    int sj = atomicAdd(&g_cnt[j], 1);
    if (sj < ELLMAX) { g_nbr[sj*NVV + j] = i; g_eid[sj*NVV + j] = e; }
}

// ---------------- launch 2: fused setup ---------------------------------------
__global__ void k_setup(const float* __restrict__ mass,
                        const float* __restrict__ pos0, const float* __restrict__ vel0,
                        const float* __restrict__ rest_len, const float* __restrict__ act) {
    const int gtid = blockIdx.x * blockDim.x + threadIdx.x;
    const int nthr = gridDim.x * blockDim.x;

    // phase 1: deterministic per-vertex adjacency sort
    for (int v = gtid; v < NVV; v += nthr) {
        int d = min(g_cnt[v], ELLMAX);
        g_deg[v] = d;
        long long key[ELLMAX];
        for (int k = 0; k < d; k++)
            key[k] = ((long long)g_nbr[k*NVV + v] << 32) | (unsigned)g_eid[k*NVV + v];
        for (int a = 1; a < d; a++) {
            long long t = key[a]; int c = a - 1;
            while (c >= 0 && key[c] > t) { key[c+1] = key[c]; c--; }
            key[c+1] = t;
        }
        for (int k = 0; k < d; k++) {
            g_nbr[k*NVV + v] = (int)(key[k] >> 32);
            g_eid[k*NVV + v] = (int)(key[k] & 0xffffffffLL);
        }
    }
    gpu_spin_barrier(&g_gbar, gridDim.x * 1u);

    // phase 2: stable counting sort by degree (CTA 0)
    if (blockIdx.x == 0) {
        __shared__ int s_cnt[64], s_off[64];
        int w = threadIdx.x >> 5, l = threadIdx.x & 31;
        #pragma unroll
        for (int pass = 0; pass < 2; pass++) {
            int d = w + pass*32;
            int cnt = 0;
            for (int b0 = 0; b0 < NVV; b0 += 32) {
                int dg = g_deg[b0 + l];
                unsigned m = __ballot_sync(0xffffffffu, dg == d);
                cnt += __popc(m);
            }
            if (l == 0) s_cnt[d] = cnt;
        }
        __syncthreads();
        if (threadIdx.x == 0) {
            int o = 0;
            for (int d = 0; d < 64; d++) { s_off[d] = o; o += s_cnt[d]; }
        }
        __syncthreads();
        #pragma unroll
        for (int pass = 0; pass < 2; pass++) {
            int d = w + pass*32;
            int off = s_off[d];
            for (int b0 = 0; b0 < NVV; b0 += 32) {
                int v = b0 + l;
                int dg = g_deg[v];
                unsigned m = __ballot_sync(0xffffffffu, dg == d);
                if (dg == d) {
                    int rank = __popc(m & ((1u << l) - 1u));
                    g_perm[off + rank] = v;
                    g_ipos[v] = off + rank;
                }
                off += __popc(m);
            }
        }
    }
    gpu_spin_barrier(&g_gbar, gridDim.x * 2u);

    // phase 3: sorted-space tables; odd tails padded with sentinel index NVV
    for (int p = gtid; p < NVV; p += nthr) {
        int v = g_perm[p];
        g_mass_p[p] = mass[v];
        int d = g_deg[v];
        g_deg_p[p] = d;
        for (int kp = 0; kp < KPAIR; kp++) {
            unsigned lo = (2*kp   < d) ? (unsigned)g_ipos[g_nbr[(2*kp  )*NVV + v]] : (unsigned)NVV;
            unsigned hi = (2*kp+1 < d) ? (unsigned)g_ipos[g_nbr[(2*kp+1)*NVV + v]] : (unsigned)NVV;
            g_nbrp[kp*NVV + p] = lo | (hi << 16);
        }
    }
    for (int idx = gtid; idx < CS; idx += nthr) {
        int p = idx & (NVV-1), b = idx >> 13;
        int v = g_perm[p];
        size_t src = ((size_t)b*NVV + v)*3;
        #pragma unroll
        for (int c = 0; c < 3; c++) {
            g_pos[c*CS + idx] = pos0[src + c];
            g_v0 [c*CS + idx] = vel0[src + c];
        }
    }
    for (int idx = gtid; idx < BB*NVV; idx += nthr) {
        int p = idx & (NVV-1), b = idx >> 13;
        int v = g_perm[p];
        int d = g_deg[v];
        for (int k = 0; k < d; k++) {
            int e = g_eid[k*NVV + v];
            g_rest[((size_t)b*ELLMAX + k)*NVV + p] = rest_len[e] * (1.f + act[(size_t)b*NEE + e]);
        }
    }
}

// ---------------- launch 3: persistent clustered solver ------------------------
__global__ void __launch_bounds__(TPB, 1) __cluster_dims__(NCTA, 1, 1)
k_main(float* __restrict__ out) {
    extern __shared__ float sm[];
    float2* s_pxy = (float2*)sm;          // NVP float2 (incl. sentinel)
    float*  s_pz  = sm + 2*NVP;           // NVP floats (incl. sentinel)
    __shared__ float s16[NW];
    __shared__ float s_ab[2];
    __shared__ float s_rs;
    __shared__ float s_mail[2];           // pAp partial mailbox, parity-buffered

    const int tid = threadIdx.x, cx = blockIdx.x, b = blockIdx.y;
    const int w = tid >> 5, l = tid & 31;
    const int base = b*NVV;

    // zero the sentinel slots (never rewritten: all updates touch [0,NVV))
    if (tid < NVP - NVV) {
        s_pxy[NVV + tid] = make_float2(0.f, 0.f);
        s_pz [NVV + tid] = 0.f;
    }

    // gather ownership: q = degree-quartile -> balanced warps & CTAs
    int pq[VPT], dq[VPT];
    float mmq[VPT];
    float PO[VPT][3], X[VPT][3];
    #pragma unroll
    for (int q = 0; q < VPT; q++) {
        int c = q*(NW*NCTA) + w*NCTA + cx;
        int p = c*32 + l;
        pq[q] = p;
        dq[q] = g_deg_p[p];
        mmq[q] = g_mass_p[p];
        int i = base + p;
        PO[q][0] = g_pos[i]; PO[q][1] = g_pos[CS+i]; PO[q][2] = g_pos[2*CS+i];
        X [q][0] = g_v0[i];  X [q][1] = g_v0[CS+i];  X [q][2] = g_v0[2*CS+i];
    }

    // register-resident residual: chunk j covers vertex j*TPB + tid
    float rX[NCH], rY[NCH], rZ[NCH];

    for (int s = 0; s < NSUB; s++) {
        // ---- stage pos into p region ----
        #pragma unroll
        for (int j = 0; j < NCH; j++) {
            int p = j*TPB + tid, i = base + p;
            s_pxy[p] = make_float2(__ldcg(&g_pos[i]), __ldcg(&g_pos[CS+i]));
            s_pz [p] = __ldcg(&g_pos[2*CS+i]);
        }
        __syncthreads();

        // ---- force, b = m v + dt f -> g_r slice (guarded tail) ----
        #pragma unroll
        for (int q = 0; q < VPT; q++) {
            int p = pq[q], i = base + p, d = dq[q];
            int np = (d + 1) >> 1;
            float fx = 0.f, fy = 0.f, fz = 0.f;
            unsigned cur = g_nbrp[p];
            for (int kp = 0; kp < np; kp++) {
                unsigned nxt = (kp+1 < np) ? g_nbrp[(kp+1)*NVV + p] : 0u;
                int u0 = cur & 0xffffu, u1 = cur >> 16;
                {
                    float2 t = s_pxy[u0];
                    float dx = PO[q][0] - t.x, dy = PO[q][1] - t.y, dz = PO[q][2] - s_pz[u0];
                    float len = sqrtf(dx*dx + dy*dy + dz*dz);
                    float rr = g_rest[((size_t)b*ELLMAX + 2*kp)*NVV + p];
                    float cc = -KSf * (len - rr) / fmaxf(len, 1e-6f);
                    fx += cc*dx; fy += cc*dy; fz += cc*dz;
                }
                if (2*kp + 1 < d) {
                    float2 t = s_pxy[u1];
                    float dx = PO[q][0] - t.x, dy = PO[q][1] - t.y, dz = PO[q][2] - s_pz[u1];
                    float len = sqrtf(dx*dx + dy*dy + dz*dz);
                    float rr = g_rest[((size_t)b*ELLMAX + 2*kp+1)*NVV + p];
                    float cc = -KSf * (len - rr) / fmaxf(len, 1e-6f);
                    fx += cc*dx; fy += cc*dy; fz += cc*dz;
                }
                cur = nxt;
            }
            float bx = mmq[q]*X[q][0] + DTf*fx;
            float by = mmq[q]*X[q][1] + DTf*(fy + mmq[q]*(-9.8f));
            float bz = mmq[q]*X[q][2] + DTf*fz;
            X[q][0] = 0.f; X[q][1] = 0.f; X[q][2] = 0.f;
            __stcg(&g_r[i], bx); __stcg(&g_r[CS+i], by); __stcg(&g_r[2*CS+i], bz);
        }
        CLUSTER_SYNC_();

        // ---- stage r -> registers, p -> smem; rs0 locally ----
        float rs_loc = 0.f;
        #pragma unroll
        for (int j = 0; j < NCH; j++) {
            int p = j*TPB + tid, i = base + p;
            float rx = __ldcg(&g_r[i]);
            float ry = __ldcg(&g_r[CS+i]);
            float rz = __ldcg(&g_r[2*CS+i]);
            rX[j] = rx; rY[j] = ry; rZ[j] = rz;
            s_pxy[p] = make_float2(rx, ry); s_pz[p] = rz;
            rs_loc += rx*rx + ry*ry + rz*rz;
        }
        __syncthreads();
        {
            float t = bredt(rs_loc, s16);
            if (tid == 0) s_rs = t;
        }
        __syncthreads();

        // ---- CG iterations ----
        for (int it = 0; it < CG_ITERS; it++) {
            const int par = it & 1;
            float4* Ap = g_Ap4[par];

            // matvec: sentinel-padded (no tail guard), canonical-order scalar adds
            float pap = 0.f;
            #pragma unroll
            for (int q = 0; q < VPT; q++) {
                int p = pq[q], i = base + p, d = dq[q];
                int np = (d + 1) >> 1;
                float sx = 0.f, sy = 0.f, sz = 0.f;
                unsigned cur = g_nbrp[p];
                for (int kp = 0; kp < np; kp++) {
                    unsigned nxt = (kp+1 < np) ? g_nbrp[(kp+1)*NVV + p] : 0u;
                    int u0 = cur & 0xffffu, u1 = cur >> 16;
                    float2 t0 = s_pxy[u0];
                    sx += t0.x; sy += t0.y; sz += s_pz[u0];
                    float2 t1 = s_pxy[u1];          // sentinel -> (+0,+0,+0), exact
                    sx += t1.x; sy += t1.y; sz += s_pz[u1];
                    cur = nxt;
                }
                float2 pv = s_pxy[p]; float pz = s_pz[p];
                float md = mmq[q] + (float)d;
                float ax = md*pv.x - sx;
                float ay = md*pv.y - sy;
                float az = md*pz   - sz;
                __stcg(&Ap[i], make_float4(ax, ay, az, 0.f));
                pap += pv.x*ax + pv.y*ay + pz*az;
            }
            {
                float t = bredt(pap, s16);
                if (tid == 0) s_mail[par] = t;
            }
            CLUSTER_SYNC_();                     // publishes s_mail + Ap slices

            if (tid == 0) {
                uint32_t ma = (uint32_t)__cvta_generic_to_shared(&s_mail[par]);
                float sp = 0.f;
                #pragma unroll
                for (int rk = 0; rk < NCTA; rk++) sp += dsmem_read_f32(ma, (uint32_t)rk);
                s_ab[0] = s_rs / (sp + 1e-12f);
            }
            __syncthreads();
            float alpha = s_ab[0];

            // x += alpha p (own slice)
            #pragma unroll
            for (int q = 0; q < VPT; q++) {
                int p = pq[q];
                float2 pv = s_pxy[p];
                X[q][0] += alpha*pv.x; X[q][1] += alpha*pv.y; X[q][2] += alpha*s_pz[p];
            }

            if (it < CG_ITERS - 1) {
                // sweep1 (registers only): r -= alpha Ap; rs_new from stored r
                float rsn_loc = 0.f;
                #pragma unroll
                for (int j = 0; j < NCH; j++) {
                    int i = base + j*TPB + tid;
                    float4 a4 = __ldcg(&Ap[i]);
                    float rx = rX[j] - alpha*a4.x;
                    float ry = rY[j] - alpha*a4.y;
                    float rz = rZ[j] - alpha*a4.z;
                    rX[j] = rx; rY[j] = ry; rZ[j] = rz;
                    rsn_loc += rx*rx + ry*ry + rz*rz;
                }
                __syncthreads();
                {
                    float t = bredt(rsn_loc, s16);
                    if (tid == 0) { s_ab[1] = t / (s_rs + 1e-12f); s_rs = t; }
                }
                __syncthreads();
                float beta = s_ab[1];
                // sweep2: p = r + beta p (r from regs; p in smem)
                #pragma unroll
                for (int j = 0; j < NCH; j++) {
                    int p = j*TPB + tid;
                    float2 po = s_pxy[p]; float poz = s_pz[p];
                    s_pxy[p] = make_float2(fmaf(beta, po.x, rX[j]),
                                           fmaf(beta, po.y, rY[j]));
                    s_pz [p] = fmaf(beta, poz, rZ[j]);
                }
                __syncthreads();
            }
        }

        // ---- pos += dt x ; emit trajectory ----
        #pragma unroll
        for (int q = 0; q < VPT; q++) {
            int p = pq[q], i = base + p;
            PO[q][0] += DTf*X[q][0];
            PO[q][1] += DTf*X[q][1];
            PO[q][2] += DTf*X[q][2];
            __stcg(&g_pos[i],      PO[q][0]);
            __stcg(&g_pos[CS+i],   PO[q][1]);
            __stcg(&g_pos[2*CS+i], PO[q][2]);
            int vorig = g_perm[p];
            size_t o = (((size_t)b*NSUB + s)*NVV + vorig)*3;
            out[o+0] = PO[q][0]; out[o+1] = PO[q][1]; out[o+2] = PO[q][2];
        }
        CLUSTER_SYNC_();
    }
}

// ---------------- launch -------------------------------------------------------
extern "C" void kernel_launch(void* const* d_in, const int* in_sizes, int n_in,
                              void* d_out, int out_size) {
    const float* act   = (const float*)d_in[0];
    const float* pos0  = (const float*)d_in[1];
    const float* vel0  = (const float*)d_in[2];
    const float* rlen  = (const float*)d_in[3];
    const float* mass  = (const float*)d_in[4];
    const int*   ei    = (const int*)d_in[5];
    const int*   ej    = (const int*)d_in[6];
    float*       out   = (float*)d_out;

    const int smbytes = 3*NVP*sizeof(float);   // ~96.2 KB (p only; r is in regs)
    static int attr_done = 0;
    if (!attr_done) {
        cudaFuncSetAttribute(k_main, cudaFuncAttributeMaxDynamicSharedMemorySize, smbytes);
        attr_done = 1;
    }

    k_pre  <<<(NVV+255)/256, 256>>>();
    k_fill <<<(NEE+255)/256, 256>>>(ei, ej);
    k_setup<<<32, 1024>>>(mass, pos0, vel0, rlen, act);
    k_main <<<dim3(NCTA, BB), TPB, smbytes>>>(out);
}